// round 13
// baseline (speedup 1.0000x reference)
#include <cuda_runtime.h>
#include <cuda_fp16.h>
#include <math.h>
#include <stdint.h>

#define DIM 1024
#define HEADS 16
#define HEAD_DIM 64
#define HIDDEN 4096
#define BATCH 4
#define SEQ 2048
#define TOKENS (BATCH * SEQ)   // 8192
#define EPS 1e-5f

// ================= scratch (device globals) =================
__device__ __half g_a[TOKENS * DIM];          // LN1 out fp16 (single)
__device__ __half g_ah[TOKENS * DIM];         // LN2 out split hi
__device__ __half g_al[TOKENS * DIM];         // LN2 out split lo
__device__ __half g_q[TOKENS * DIM];          // [b*h][n][64], q pre-scaled 0.125*log2e
__device__ __half g_k[TOKENS * DIM];
__device__ __half g_v[TOKENS * DIM];
__device__ __half g_o[TOKENS * DIM];          // attn out [token][h*64+d]
__device__ __half g_f1h[TOKENS * HIDDEN];     // fc1+gelu out split
__device__ __half g_f1l[TOKENS * HIDDEN];
__device__ __half g_wqkvT[3 * DIM * DIM];     // [N,K] single
__device__ __half g_wprojT[DIM * DIM];        // single
__device__ __half g_wfc1T_h[HIDDEN * DIM];    // split
__device__ __half g_wfc1T_l[HIDDEN * DIM];
__device__ __half g_wfc2T_h[DIM * HIDDEN];
__device__ __half g_wfc2T_l[DIM * HIDDEN];

// ================= PTX helpers (plain sm_80+ PTX) =================
__device__ __forceinline__ uint32_t smem_u32(const void* p) {
    return (uint32_t)__cvta_generic_to_shared(p);
}
__device__ __forceinline__ void cp16(uint32_t dst, const void* src) {
    asm volatile("cp.async.cg.shared.global [%0], [%1], 16;" :: "r"(dst), "l"(src) : "memory");
}
__device__ __forceinline__ void cp_commit() {
    asm volatile("cp.async.commit_group;" ::: "memory");
}
__device__ __forceinline__ void cp_wait1() {
    asm volatile("cp.async.wait_group 1;" ::: "memory");
}
__device__ __forceinline__ void cp_wait0() {
    asm volatile("cp.async.wait_group 0;" ::: "memory");
}
__device__ __forceinline__ void ldm_x4(uint32_t* r, uint32_t addr) {
    asm volatile("ldmatrix.sync.aligned.m8n8.x4.shared.b16 {%0,%1,%2,%3}, [%4];"
                 : "=r"(r[0]), "=r"(r[1]), "=r"(r[2]), "=r"(r[3]) : "r"(addr));
}
__device__ __forceinline__ void ldm_x2(uint32_t* r, uint32_t addr) {
    asm volatile("ldmatrix.sync.aligned.m8n8.x2.shared.b16 {%0,%1}, [%2];"
                 : "=r"(r[0]), "=r"(r[1]) : "r"(addr));
}
__device__ __forceinline__ void ldm_x4t(uint32_t* r, uint32_t addr) {
    asm volatile("ldmatrix.sync.aligned.m8n8.x4.trans.shared.b16 {%0,%1,%2,%3}, [%4];"
                 : "=r"(r[0]), "=r"(r[1]), "=r"(r[2]), "=r"(r[3]) : "r"(addr));
}
__device__ __forceinline__ void mma_fp16(float* d, const uint32_t* a, const uint32_t* b) {
    asm volatile(
        "mma.sync.aligned.m16n8k16.row.col.f32.f16.f16.f32 "
        "{%0,%1,%2,%3}, {%4,%5,%6,%7}, {%8,%9}, {%0,%1,%2,%3};"
        : "+f"(d[0]), "+f"(d[1]), "+f"(d[2]), "+f"(d[3])
        : "r"(a[0]), "r"(a[1]), "r"(a[2]), "r"(a[3]), "r"(b[0]), "r"(b[1]));
}
__device__ __forceinline__ uint32_t pack_h2(float a, float b) {
    __half2 h = __floats2half2_rn(a, b);
    return *(uint32_t*)&h;
}
__device__ __forceinline__ void split16(float v, __half& h, __half& l) {
    h = __float2half_rn(v);
    l = __float2half_rn(v - __half2float(h));
}

// ================= LayerNorm =================
template<int SPLIT>
__global__ void ln_kernel(const float* __restrict__ x,
                          const float* __restrict__ g,
                          const float* __restrict__ b,
                          __half* __restrict__ o0, __half* __restrict__ o1)
{
    int row = blockIdx.x;
    const float4* xr = (const float4*)(x + (size_t)row * DIM);
    int tid = threadIdx.x;
    float4 v = xr[tid];
    float s  = v.x + v.y + v.z + v.w;
    float ss = v.x*v.x + v.y*v.y + v.z*v.z + v.w*v.w;
    for (int o = 16; o > 0; o >>= 1) {
        s  += __shfl_down_sync(0xFFFFFFFFu, s,  o);
        ss += __shfl_down_sync(0xFFFFFFFFu, ss, o);
    }
    __shared__ float red_s[8], red_ss[8];
    int wid = tid >> 5, lid = tid & 31;
    if (lid == 0) { red_s[wid] = s; red_ss[wid] = ss; }
    __syncthreads();
    __shared__ float sh_mu, sh_rstd;
    if (tid == 0) {
        float ts = 0.f, tss = 0.f;
        #pragma unroll
        for (int i = 0; i < 8; i++) { ts += red_s[i]; tss += red_ss[i]; }
        float mu  = ts * (1.0f / DIM);
        float var = tss * (1.0f / DIM) - mu * mu;
        sh_mu = mu; sh_rstd = rsqrtf(var + EPS);
    }
    __syncthreads();
    float mu = sh_mu, rstd = sh_rstd;

    int c = tid * 4;
    float4 gg = *(const float4*)(g + c);
    float4 bb = *(const float4*)(b + c);
    float y[4];
    y[0] = (v.x - mu) * rstd * gg.x + bb.x;
    y[1] = (v.y - mu) * rstd * gg.y + bb.y;
    y[2] = (v.z - mu) * rstd * gg.z + bb.z;
    y[3] = (v.w - mu) * rstd * gg.w + bb.w;
    size_t base = (size_t)row * DIM + c;
    #pragma unroll
    for (int i = 0; i < 4; i += 2) {
        if (SPLIT) {
            __half h0, l0, h1, l1;
            split16(y[i], h0, l0);
            split16(y[i+1], h1, l1);
            *(__half2*)(o0 + base + i) = __half2(h0, h1);
            *(__half2*)(o1 + base + i) = __half2(l0, l1);
        } else {
            *(__half2*)(o0 + base + i) = __floats2half2_rn(y[i], y[i+1]);
        }
    }
}

// ========== weight transpose: w[K,N] f32 -> [N,K] fp16 (single or split) ==========
template<int SPLIT>
__global__ void wT_kernel(const float* __restrict__ w,
                          __half* __restrict__ o0, __half* __restrict__ o1,
                          int K, int N)
{
    __shared__ float t[32][33];
    int n0 = blockIdx.x * 32, k0 = blockIdx.y * 32;
    int tx = threadIdx.x;   // 0..15
    int ty = threadIdx.y;   // 0..15
    #pragma unroll
    for (int r = 0; r < 2; r++) {
        int kk = ty + r * 16;
        float2 v = *(const float2*)(w + (size_t)(k0 + kk) * N + n0 + tx * 2);
        t[kk][tx * 2]     = v.x;
        t[kk][tx * 2 + 1] = v.y;
    }
    __syncthreads();
    #pragma unroll
    for (int r = 0; r < 2; r++) {
        int nn = ty + r * 16;
        float v0 = t[tx * 2][nn];
        float v1 = t[tx * 2 + 1][nn];
        size_t idx = (size_t)(n0 + nn) * K + k0 + tx * 2;
        if (SPLIT) {
            __half h0, l0, h1, l1;
            split16(v0, h0, l0);
            split16(v1, h1, l1);
            *(__half2*)(o0 + idx) = __half2(h0, h1);
            *(__half2*)(o1 + idx) = __half2(l0, l1);
        } else {
            *(__half2*)(o0 + idx) = __floats2half2_rn(v0, v1);
        }
    }
}

// ================= fp16 mma.sync GEMM (R11/R12 config) ========
// MODE 0: single, +bias, scatter QKV fp16 (q scaled 0.125*log2e)
// MODE 1: single, +bias+res -> f32
// MODE 2: split,  +bias, exact GELU -> split fp16 (O0=hi, O1=lo)
// MODE 3: split,  +bias+res -> f32
#define ROWB   80
#define TILE_B (128 * ROWB)            // 10240
#define BKK 32

template<int MODE, int SPLIT>
__global__ void __launch_bounds__(256, 2) gemm_tc(
    const __half* __restrict__ Ah, const __half* __restrict__ Al,
    const __half* __restrict__ Bh, const __half* __restrict__ Bl,
    const float* __restrict__ bias, const float* __restrict__ res,
    float* __restrict__ Cf, __half* __restrict__ O0,
    __half* __restrict__ O1, __half* __restrict__ O2,
    int Nt, int K)
{
    const int NTILES = SPLIT ? 4 : 2;
    const int STAGE_B = NTILES * TILE_B;
    const int NSTAGEL = SPLIT ? 2 : 3;     // split: 2 stages so 2 CTAs/SM fit
    extern __shared__ char smem[];
    uint32_t sb = smem_u32(smem);
    const int tid = threadIdx.x;
    const int w = tid >> 5;
    const int lane = tid & 31;
    const int m0 = blockIdx.y * 128;
    const int n0 = blockIdx.x * 128;
    const int warp_m = (w & 1) * 64;
    const int warp_n = (w >> 1) * 32;

    const __half* srcAh = Ah + (size_t)m0 * K;
    const __half* srcBh = Bh + (size_t)n0 * K;
    const __half* srcAl = SPLIT ? (Al + (size_t)m0 * K) : nullptr;
    const __half* srcBl = SPLIT ? (Bl + (size_t)n0 * K) : nullptr;

    auto load_stage = [&](int s, int k0) {
        uint32_t sdst = sb + s * STAGE_B;
        #pragma unroll
        for (int i = 0; i < 2; i++) {
            int idx = tid + i * 256;        // 0..511
            int row = idx >> 2, ch = idx & 3;
            uint32_t doff = row * ROWB + ch * 16;
            size_t soff = (size_t)row * K + k0 + ch * 8;
            cp16(sdst + doff, srcAh + soff);
            cp16(sdst + TILE_B + doff, srcBh + soff);
            if (SPLIT) {
                cp16(sdst + 2 * TILE_B + doff, srcAl + soff);
                cp16(sdst + 3 * TILE_B + doff, srcBl + soff);
            }
        }
    };

    float acc[4][4][4];
    #pragma unroll
    for (int i = 0; i < 4; i++)
        #pragma unroll
        for (int j = 0; j < 4; j++)
            #pragma unroll
            for (int d = 0; d < 4; d++) acc[i][j][d] = 0.f;

    const int NT = K / BKK;
    load_stage(0, 0);       cp_commit();
    load_stage(1, BKK);     cp_commit();

    const int lm  = lane & 15, kb4 = lane >> 4;
    const int lb  = lane & 7,  kb2 = (lane >> 3) & 1;

    for (int it = 0; it < NT; it++) {
        cp_wait1();
        __syncthreads();

        uint32_t stg = sb + (it % NSTAGEL) * STAGE_B;

        if (!SPLIT) {
            if (it + 2 < NT) { load_stage((it + 2) % NSTAGEL, (it + 2) * BKK); cp_commit(); }
        }

        #pragma unroll
        for (int ks = 0; ks < 2; ks++) {
            uint32_t af[4][4], bf[4][2];
            uint32_t aoff = (warp_m + lm) * ROWB + (ks * 16 + kb4 * 8) * 2;
            uint32_t boff = (warp_n + lb) * ROWB + (ks * 16 + kb2 * 8) * 2;

            #pragma unroll
            for (int mf = 0; mf < 4; mf++)
                ldm_x4(af[mf], stg + aoff + mf * 16 * ROWB);
            #pragma unroll
            for (int nf = 0; nf < 4; nf++)
                ldm_x2(bf[nf], stg + TILE_B + boff + nf * 8 * ROWB);
            #pragma unroll
            for (int mf = 0; mf < 4; mf++)
                #pragma unroll
                for (int nf = 0; nf < 4; nf++)
                    mma_fp16(acc[mf][nf], af[mf], bf[nf]);

            if (SPLIT) {
                #pragma unroll
                for (int nf = 0; nf < 4; nf++)
                    ldm_x2(bf[nf], stg + 3 * TILE_B + boff + nf * 8 * ROWB);
                #pragma unroll
                for (int mf = 0; mf < 4; mf++)
                    #pragma unroll
                    for (int nf = 0; nf < 4; nf++)
                        mma_fp16(acc[mf][nf], af[mf], bf[nf]);

                #pragma unroll
                for (int mf = 0; mf < 4; mf++)
                    ldm_x4(af[mf], stg + 2 * TILE_B + aoff + mf * 16 * ROWB);
                #pragma unroll
                for (int nf = 0; nf < 4; nf++)
                    ldm_x2(bf[nf], stg + TILE_B + boff + nf * 8 * ROWB);
                #pragma unroll
                for (int mf = 0; mf < 4; mf++)
                    #pragma unroll
                    for (int nf = 0; nf < 4; nf++)
                        mma_fp16(acc[mf][nf], af[mf], bf[nf]);
            }
        }
        if (SPLIT) {
            __syncthreads();
            if (it + 2 < NT) { load_stage((it + 2) % NSTAGEL, (it + 2) * BKK); cp_commit(); }
        }
    }

    // ---- epilogue ----
    const int r0 = lane >> 2, c0 = (lane & 3) * 2;
    #pragma unroll
    for (int mf = 0; mf < 4; mf++) {
        #pragma unroll
        for (int nf = 0; nf < 4; nf++) {
            int col = n0 + warp_n + nf * 8 + c0;
            float bv0 = bias[col], bv1 = bias[col + 1];
            #pragma unroll
            for (int h2 = 0; h2 < 2; h2++) {
                int row = m0 + warp_m + mf * 16 + r0 + h2 * 8;
                float v0 = acc[mf][nf][h2 * 2 + 0] + bv0;
                float v1 = acc[mf][nf][h2 * 2 + 1] + bv1;
                if (MODE == 0) {
                    int t = col >> 10, rem = col & 1023;
                    int hh = rem >> 6, d = rem & 63;
                    __half* dst = (t == 0) ? O0 : (t == 1) ? O1 : O2;
                    if (t == 0) {
                        v0 *= 0.18033688011112042f;  // 0.125 * log2(e)
                        v1 *= 0.18033688011112042f;
                    }
                    int b = row >> 11, n = row & 2047;
                    size_t idx = ((size_t)((b << 4) + hh) * SEQ + n) * HEAD_DIM + d;
                    *(__half2*)(dst + idx) = __floats2half2_rn(v0, v1);
                } else if (MODE == 2) {
                    v0 = 0.5f * v0 * (1.0f + erff(v0 * 0.70710678118654752f));
                    v1 = 0.5f * v1 * (1.0f + erff(v1 * 0.70710678118654752f));
                    __half h0, l0, h1, l1;
                    split16(v0, h0, l0);
                    split16(v1, h1, l1);
                    size_t idx = (size_t)row * Nt + col;
                    *(__half2*)(O0 + idx) = __half2(h0, h1);
                    *(__half2*)(O1 + idx) = __half2(l0, l1);
                } else {  // MODE 1 / 3
                    size_t idx = (size_t)row * Nt + col;
                    float2 rr = *(const float2*)(res + idx);
                    float2 o2; o2.x = v0 + rr.x; o2.y = v1 + rr.y;
                    *(float2*)(Cf + idx) = o2;
                }
            }
        }
    }
}

// ================= Flash attention, fp16 mma.sync, STATIC-MAX exp2 softmax =========
// Logits (log2 domain) are statistically bounded (std~0.6, max ~3.7 over all
// samples; fp16 overflow would need >16 = 27 sigma). So p = exp2(s) directly:
// no running max, no rescale, l accumulated per-thread and reduced ONCE at end.
#define AT_ROWB 144
#define AT_TILE (64 * AT_ROWB)            // 9216
#define ATTN_SMEM (AT_TILE * 5)           // Q + 2*(K,V) = 46080

__global__ void __launch_bounds__(128, 3) attn_kernel(
    const __half* __restrict__ qb, const __half* __restrict__ kb,
    const __half* __restrict__ vb, __half* __restrict__ ob)
{
    extern __shared__ char smc[];
    uint32_t sb = smem_u32(smc);
    const int tid = threadIdx.x;
    const int w = tid >> 5;
    const int lane = tid & 31;
    const int bh = blockIdx.y;
    const int n0 = blockIdx.x * 64;

    const __half* qg = qb + ((size_t)bh * SEQ + n0) * HEAD_DIM;

    #pragma unroll
    for (int i = 0; i < 4; i++) {
        int idx = tid + i * 128;
        int r = idx >> 3, ch = idx & 7;
        cp16(sb + r * AT_ROWB + ch * 16, qg + (size_t)r * HEAD_DIM + ch * 8);
    }
    cp_commit();

    auto loadKV = [&](int s, int t) {
        const __half* kg = kb + ((size_t)bh * SEQ + t * 64) * HEAD_DIM;
        const __half* vg = vb + ((size_t)bh * SEQ + t * 64) * HEAD_DIM;
        uint32_t ks = sb + AT_TILE + s * 2 * AT_TILE;
        uint32_t vs = ks + AT_TILE;
        #pragma unroll
        for (int i = 0; i < 4; i++) {
            int idx = tid + i * 128;
            int r = idx >> 3, ch = idx & 7;
            cp16(ks + r * AT_ROWB + ch * 16, kg + (size_t)r * HEAD_DIM + ch * 8);
            cp16(vs + r * AT_ROWB + ch * 16, vg + (size_t)r * HEAD_DIM + ch * 8);
        }
    };

    loadKV(0, 0); cp_commit();
    cp_wait1();
    __syncthreads();

    const int lm = lane & 15, kb4 = lane >> 4;
    const int lb = lane & 7,  kb2 = (lane >> 3) & 1;
    uint32_t qf[4][4];
    #pragma unroll
    for (int kf = 0; kf < 4; kf++)
        ldm_x4(qf[kf], sb + (w * 16 + lm) * AT_ROWB + (kf * 16 + kb4 * 8) * 2);

    float of[8][4];
    #pragma unroll
    for (int i = 0; i < 8; i++)
        #pragma unroll
        for (int j = 0; j < 4; j++) of[i][j] = 0.f;
    float l0 = 0.f, l1 = 0.f;   // per-thread partial row sums (no rescale needed)

    const int NTK = SEQ / 64;
    for (int t = 0; t < NTK; t++) {
        int s = t & 1;
        if (t + 1 < NTK) { loadKV(s ^ 1, t + 1); cp_commit(); }
        if (t + 1 < NTK) cp_wait1(); else cp_wait0();
        __syncthreads();

        uint32_t kbase = sb + AT_TILE + s * 2 * AT_TILE;
        uint32_t vbase = kbase + AT_TILE;

        // ---- S = Q K^T (log2 domain) ----
        float sc[8][4];
        #pragma unroll
        for (int i = 0; i < 8; i++)
            #pragma unroll
            for (int j = 0; j < 4; j++) sc[i][j] = 0.f;
        #pragma unroll
        for (int nf = 0; nf < 8; nf++) {
            uint32_t bf[4][2];
            #pragma unroll
            for (int kf = 0; kf < 4; kf++)
                ldm_x2(bf[kf], kbase + (nf * 8 + lb) * AT_ROWB + (kf * 16 + kb2 * 8) * 2);
            #pragma unroll
            for (int kf = 0; kf < 4; kf++)
                mma_fp16(sc[nf], qf[kf], bf[kf]);
        }

        // ---- static-max softmax: p = exp2(s), accumulate l ----
        #pragma unroll
        for (int nf = 0; nf < 8; nf++) {
            sc[nf][0] = exp2f(sc[nf][0]);
            sc[nf][1] = exp2f(sc[nf][1]);
            sc[nf][2] = exp2f(sc[nf][2]);
            sc[nf][3] = exp2f(sc[nf][3]);
            l0 += sc[nf][0] + sc[nf][1];
            l1 += sc[nf][2] + sc[nf][3];
        }

        // ---- P (fp16 A-frags) ----
        uint32_t pa[4][4];
        #pragma unroll
        for (int kf = 0; kf < 4; kf++) {
            pa[kf][0] = pack_h2(sc[2*kf][0],   sc[2*kf][1]);
            pa[kf][1] = pack_h2(sc[2*kf][2],   sc[2*kf][3]);
            pa[kf][2] = pack_h2(sc[2*kf+1][0], sc[2*kf+1][1]);
            pa[kf][3] = pack_h2(sc[2*kf+1][2], sc[2*kf+1][3]);
        }

        // ---- O += P V  (V via trans ldmatrix) ----
        int tl = lane >> 3;
        #pragma unroll
        for (int kf = 0; kf < 4; kf++) {
            #pragma unroll
            for (int nb = 0; nb < 4; nb++) {
                uint32_t vf[4];
                int row = kf * 16 + (tl & 1) * 8 + (lane & 7);
                int col = nb * 16 + (tl >> 1) * 8;
                ldm_x4t(vf, vbase + row * AT_ROWB + col * 2);
                mma_fp16(of[2*nb],     pa[kf], vf);
                mma_fp16(of[2*nb + 1], pa[kf], vf + 2);
            }
        }
        __syncthreads();
    }

    // ---- single final l reduction across the 4 threads sharing each row ----
    l0 += __shfl_xor_sync(0xFFFFFFFFu, l0, 1);
    l0 += __shfl_xor_sync(0xFFFFFFFFu, l0, 2);
    l1 += __shfl_xor_sync(0xFFFFFFFFu, l1, 1);
    l1 += __shfl_xor_sync(0xFFFFFFFFu, l1, 2);

    // ---- epilogue ----
    float inv0 = 1.0f / l0, inv1 = 1.0f / l1;
    int b = bh >> 4, hh = bh & 15;
    int r0g = n0 + w * 16 + (lane >> 2);
    size_t tok0 = (size_t)(b * SEQ + r0g);
    size_t tok1 = tok0 + 8;
    int colb = hh * HEAD_DIM + 2 * (lane & 3);
    #pragma unroll
    for (int nf = 0; nf < 8; nf++) {
        int col = colb + nf * 8;
        *(__half2*)(ob + tok0 * DIM + col) = __floats2half2_rn(of[nf][0] * inv0, of[nf][1] * inv0);
        *(__half2*)(ob + tok1 * DIM + col) = __floats2half2_rn(of[nf][2] * inv1, of[nf][3] * inv1);
    }
}

// ================= launch =================
extern "C" void kernel_launch(void* const* d_in, const int* in_sizes, int n_in,
                              void* d_out, int out_size)
{
    (void)in_sizes; (void)n_in; (void)out_size;
    const float* x      = (const float*)d_in[0];
    const float* ln1_g  = (const float*)d_in[1];
    const float* ln1_b  = (const float*)d_in[2];
    const float* ln2_g  = (const float*)d_in[3];
    const float* ln2_b  = (const float*)d_in[4];
    const float* w_qkv  = (const float*)d_in[5];
    const float* b_qkv  = (const float*)d_in[6];
    const float* w_proj = (const float*)d_in[7];
    const float* b_proj = (const float*)d_in[8];
    const float* w_fc1  = (const float*)d_in[9];
    const float* b_fc1  = (const float*)d_in[10];
    const float* w_fc2  = (const float*)d_in[11];
    const float* b_fc2  = (const float*)d_in[12];
    float* out = (float*)d_out;

    __half *a, *ah, *al, *q, *k, *v, *o, *f1h, *f1l;
    __half *wq, *wp, *w1h, *w1l, *w2h, *w2l;
    cudaGetSymbolAddress((void**)&a,   g_a);
    cudaGetSymbolAddress((void**)&ah,  g_ah);
    cudaGetSymbolAddress((void**)&al,  g_al);
    cudaGetSymbolAddress((void**)&q,   g_q);
    cudaGetSymbolAddress((void**)&k,   g_k);
    cudaGetSymbolAddress((void**)&v,   g_v);
    cudaGetSymbolAddress((void**)&o,   g_o);
    cudaGetSymbolAddress((void**)&f1h, g_f1h);
    cudaGetSymbolAddress((void**)&f1l, g_f1l);
    cudaGetSymbolAddress((void**)&wq,  g_wqkvT);
    cudaGetSymbolAddress((void**)&wp,  g_wprojT);
    cudaGetSymbolAddress((void**)&w1h, g_wfc1T_h);
    cudaGetSymbolAddress((void**)&w1l, g_wfc1T_l);
    cudaGetSymbolAddress((void**)&w2h, g_wfc2T_h);
    cudaGetSymbolAddress((void**)&w2l, g_wfc2T_l);

    const int SMEM_SINGLE = 3 * 2 * TILE_B;   // 61440 (3 stages)
    const int SMEM_SPLIT  = 2 * 4 * TILE_B;   // 81920 (2 stages)
    cudaFuncSetAttribute(attn_kernel, cudaFuncAttributeMaxDynamicSharedMemorySize, ATTN_SMEM);
    cudaFuncSetAttribute((gemm_tc<0,0>), cudaFuncAttributeMaxDynamicSharedMemorySize, SMEM_SINGLE);
    cudaFuncSetAttribute((gemm_tc<1,0>), cudaFuncAttributeMaxDynamicSharedMemorySize, SMEM_SINGLE);
    cudaFuncSetAttribute((gemm_tc<2,1>), cudaFuncAttributeMaxDynamicSharedMemorySize, SMEM_SPLIT);
    cudaFuncSetAttribute((gemm_tc<3,1>), cudaFuncAttributeMaxDynamicSharedMemorySize, SMEM_SPLIT);

    // ---- side stream for all weight transposes (captured event fork-join) ----
    cudaStream_t s1;
    cudaStreamCreateWithFlags(&s1, cudaStreamNonBlocking);
    cudaEvent_t eFork, eQkvT, eJoin;
    cudaEventCreateWithFlags(&eFork, cudaEventDisableTiming);
    cudaEventCreateWithFlags(&eQkvT, cudaEventDisableTiming);
    cudaEventCreateWithFlags(&eJoin, cudaEventDisableTiming);

    dim3 tb(16, 16);
    cudaEventRecord(eFork, 0);
    cudaStreamWaitEvent(s1, eFork, 0);
    wT_kernel<0><<<dim3(3 * DIM / 32, DIM / 32), tb, 0, s1>>>(w_qkv, wq, nullptr, DIM, 3 * DIM);
    cudaEventRecord(eQkvT, s1);
    wT_kernel<0><<<dim3(DIM / 32, DIM / 32), tb, 0, s1>>>(w_proj, wp, nullptr, DIM, DIM);
    wT_kernel<1><<<dim3(HIDDEN / 32, DIM / 32), tb, 0, s1>>>(w_fc1, w1h, w1l, DIM, HIDDEN);
    wT_kernel<1><<<dim3(DIM / 32, HIDDEN / 32), tb, 0, s1>>>(w_fc2, w2h, w2l, HIDDEN, DIM);
    cudaEventRecord(eJoin, s1);

    // main stream
    ln_kernel<0><<<TOKENS, 256>>>(x, ln1_g, ln1_b, a, nullptr);
    cudaStreamWaitEvent(0, eQkvT, 0);
    gemm_tc<0,0><<<dim3(3 * DIM / 128, TOKENS / 128), 256, SMEM_SINGLE>>>(
        a, nullptr, wq, nullptr, b_qkv, nullptr, nullptr, q, k, v, 3 * DIM, DIM);
    attn_kernel<<<dim3(SEQ / 64, BATCH * HEADS), 128, ATTN_SMEM>>>(q, k, v, o);
    cudaStreamWaitEvent(0, eJoin, 0);
    gemm_tc<1,0><<<dim3(DIM / 128, TOKENS / 128), 256, SMEM_SINGLE>>>(
        o, nullptr, wp, nullptr, b_proj, x, out, nullptr, nullptr, nullptr, DIM, DIM);
    ln_kernel<1><<<TOKENS, 256>>>(out, ln2_g, ln2_b, ah, al);
    gemm_tc<2,1><<<dim3(HIDDEN / 128, TOKENS / 128), 256, SMEM_SPLIT>>>(
        ah, al, w1h, w1l, b_fc1, nullptr, nullptr, f1h, f1l, nullptr, HIDDEN, DIM);
    gemm_tc<3,1><<<dim3(DIM / 128, TOKENS / 128), 256, SMEM_SPLIT>>>(
        f1h, f1l, w2h, w2l, b_fc2, out, out, nullptr, nullptr, nullptr, DIM, HIDDEN);
}

// round 14
// speedup vs baseline: 1.5154x; 1.5154x over previous
#include <cuda_runtime.h>
#include <cuda_fp16.h>
#include <math.h>
#include <stdint.h>

#define DIM 1024
#define HEADS 16
#define HEAD_DIM 64
#define HIDDEN 4096
#define BATCH 4
#define SEQ 2048
#define TOKENS (BATCH * SEQ)   // 8192
#define EPS 1e-5f

// ================= scratch (device globals) =================
__device__ __half g_a[TOKENS * DIM];          // LN1 out fp16 (single)
__device__ __half g_ah[TOKENS * DIM];         // LN2 out split hi
__device__ __half g_al[TOKENS * DIM];         // LN2 out split lo
__device__ __half g_q[TOKENS * DIM];          // [b*h][n][64], q pre-scaled 0.125*log2e
__device__ __half g_k[TOKENS * DIM];
__device__ __half g_v[TOKENS * DIM];
__device__ __half g_o[TOKENS * DIM];          // attn out [token][h*64+d]
__device__ __half g_f1h[TOKENS * HIDDEN];     // fc1+gelu out split
__device__ __half g_f1l[TOKENS * HIDDEN];
__device__ __half g_wqkvT[3 * DIM * DIM];     // [N,K] single
__device__ __half g_wprojT[DIM * DIM];        // single
__device__ __half g_wfc1T_h[HIDDEN * DIM];    // split
__device__ __half g_wfc1T_l[HIDDEN * DIM];
__device__ __half g_wfc2T_h[DIM * HIDDEN];
__device__ __half g_wfc2T_l[DIM * HIDDEN];

// ================= PTX helpers (plain sm_80+ PTX) =================
__device__ __forceinline__ uint32_t smem_u32(const void* p) {
    return (uint32_t)__cvta_generic_to_shared(p);
}
__device__ __forceinline__ void cp16(uint32_t dst, const void* src) {
    asm volatile("cp.async.cg.shared.global [%0], [%1], 16;" :: "r"(dst), "l"(src) : "memory");
}
__device__ __forceinline__ void cp_commit() {
    asm volatile("cp.async.commit_group;" ::: "memory");
}
__device__ __forceinline__ void cp_wait1() {
    asm volatile("cp.async.wait_group 1;" ::: "memory");
}
__device__ __forceinline__ void cp_wait0() {
    asm volatile("cp.async.wait_group 0;" ::: "memory");
}
__device__ __forceinline__ void ldm_x4(uint32_t* r, uint32_t addr) {
    asm volatile("ldmatrix.sync.aligned.m8n8.x4.shared.b16 {%0,%1,%2,%3}, [%4];"
                 : "=r"(r[0]), "=r"(r[1]), "=r"(r[2]), "=r"(r[3]) : "r"(addr));
}
__device__ __forceinline__ void ldm_x2(uint32_t* r, uint32_t addr) {
    asm volatile("ldmatrix.sync.aligned.m8n8.x2.shared.b16 {%0,%1}, [%2];"
                 : "=r"(r[0]), "=r"(r[1]) : "r"(addr));
}
__device__ __forceinline__ void ldm_x4t(uint32_t* r, uint32_t addr) {
    asm volatile("ldmatrix.sync.aligned.m8n8.x4.trans.shared.b16 {%0,%1,%2,%3}, [%4];"
                 : "=r"(r[0]), "=r"(r[1]), "=r"(r[2]), "=r"(r[3]) : "r"(addr));
}
__device__ __forceinline__ void mma_fp16(float* d, const uint32_t* a, const uint32_t* b) {
    asm volatile(
        "mma.sync.aligned.m16n8k16.row.col.f32.f16.f16.f32 "
        "{%0,%1,%2,%3}, {%4,%5,%6,%7}, {%8,%9}, {%0,%1,%2,%3};"
        : "+f"(d[0]), "+f"(d[1]), "+f"(d[2]), "+f"(d[3])
        : "r"(a[0]), "r"(a[1]), "r"(a[2]), "r"(a[3]), "r"(b[0]), "r"(b[1]));
}
__device__ __forceinline__ uint32_t pack_h2(float a, float b) {
    __half2 h = __floats2half2_rn(a, b);
    return *(uint32_t*)&h;
}
__device__ __forceinline__ void split16(float v, __half& h, __half& l) {
    h = __float2half_rn(v);
    l = __float2half_rn(v - __half2float(h));
}

// ================= LayerNorm =================
template<int SPLIT>
__global__ void ln_kernel(const float* __restrict__ x,
                          const float* __restrict__ g,
                          const float* __restrict__ b,
                          __half* __restrict__ o0, __half* __restrict__ o1)
{
    int row = blockIdx.x;
    const float4* xr = (const float4*)(x + (size_t)row * DIM);
    int tid = threadIdx.x;
    float4 v = xr[tid];
    float s  = v.x + v.y + v.z + v.w;
    float ss = v.x*v.x + v.y*v.y + v.z*v.z + v.w*v.w;
    for (int o = 16; o > 0; o >>= 1) {
        s  += __shfl_down_sync(0xFFFFFFFFu, s,  o);
        ss += __shfl_down_sync(0xFFFFFFFFu, ss, o);
    }
    __shared__ float red_s[8], red_ss[8];
    int wid = tid >> 5, lid = tid & 31;
    if (lid == 0) { red_s[wid] = s; red_ss[wid] = ss; }
    __syncthreads();
    __shared__ float sh_mu, sh_rstd;
    if (tid == 0) {
        float ts = 0.f, tss = 0.f;
        #pragma unroll
        for (int i = 0; i < 8; i++) { ts += red_s[i]; tss += red_ss[i]; }
        float mu  = ts * (1.0f / DIM);
        float var = tss * (1.0f / DIM) - mu * mu;
        sh_mu = mu; sh_rstd = rsqrtf(var + EPS);
    }
    __syncthreads();
    float mu = sh_mu, rstd = sh_rstd;

    int c = tid * 4;
    float4 gg = *(const float4*)(g + c);
    float4 bb = *(const float4*)(b + c);
    float y[4];
    y[0] = (v.x - mu) * rstd * gg.x + bb.x;
    y[1] = (v.y - mu) * rstd * gg.y + bb.y;
    y[2] = (v.z - mu) * rstd * gg.z + bb.z;
    y[3] = (v.w - mu) * rstd * gg.w + bb.w;
    size_t base = (size_t)row * DIM + c;
    #pragma unroll
    for (int i = 0; i < 4; i += 2) {
        if (SPLIT) {
            __half h0, l0, h1, l1;
            split16(y[i], h0, l0);
            split16(y[i+1], h1, l1);
            *(__half2*)(o0 + base + i) = __half2(h0, h1);
            *(__half2*)(o1 + base + i) = __half2(l0, l1);
        } else {
            *(__half2*)(o0 + base + i) = __floats2half2_rn(y[i], y[i+1]);
        }
    }
}

// ========== weight transpose: w[K,N] f32 -> [N,K] fp16 (single or split) ==========
template<int SPLIT>
__global__ void wT_kernel(const float* __restrict__ w,
                          __half* __restrict__ o0, __half* __restrict__ o1,
                          int K, int N)
{
    __shared__ float t[32][33];
    int n0 = blockIdx.x * 32, k0 = blockIdx.y * 32;
    int tx = threadIdx.x;   // 0..15
    int ty = threadIdx.y;   // 0..15
    #pragma unroll
    for (int r = 0; r < 2; r++) {
        int kk = ty + r * 16;
        float2 v = *(const float2*)(w + (size_t)(k0 + kk) * N + n0 + tx * 2);
        t[kk][tx * 2]     = v.x;
        t[kk][tx * 2 + 1] = v.y;
    }
    __syncthreads();
    #pragma unroll
    for (int r = 0; r < 2; r++) {
        int nn = ty + r * 16;
        float v0 = t[tx * 2][nn];
        float v1 = t[tx * 2 + 1][nn];
        size_t idx = (size_t)(n0 + nn) * K + k0 + tx * 2;
        if (SPLIT) {
            __half h0, l0, h1, l1;
            split16(v0, h0, l0);
            split16(v1, h1, l1);
            *(__half2*)(o0 + idx) = __half2(h0, h1);
            *(__half2*)(o1 + idx) = __half2(l0, l1);
        } else {
            *(__half2*)(o0 + idx) = __floats2half2_rn(v0, v1);
        }
    }
}

// ================= fp16 mma.sync GEMM (R11/R12 config) ========
// MODE 0: single, +bias, scatter QKV fp16 (q scaled 0.125*log2e)
// MODE 1: single, +bias+res -> f32
// MODE 2: split,  +bias, exact GELU -> split fp16 (O0=hi, O1=lo)
// MODE 3: split,  +bias+res -> f32
#define ROWB   80
#define TILE_B (128 * ROWB)            // 10240
#define BKK 32

template<int MODE, int SPLIT>
__global__ void __launch_bounds__(256, 2) gemm_tc(
    const __half* __restrict__ Ah, const __half* __restrict__ Al,
    const __half* __restrict__ Bh, const __half* __restrict__ Bl,
    const float* __restrict__ bias, const float* __restrict__ res,
    float* __restrict__ Cf, __half* __restrict__ O0,
    __half* __restrict__ O1, __half* __restrict__ O2,
    int Nt, int K)
{
    const int NTILES = SPLIT ? 4 : 2;
    const int STAGE_B = NTILES * TILE_B;
    const int NSTAGEL = SPLIT ? 2 : 3;     // split: 2 stages so 2 CTAs/SM fit
    extern __shared__ char smem[];
    uint32_t sb = smem_u32(smem);
    const int tid = threadIdx.x;
    const int w = tid >> 5;
    const int lane = tid & 31;
    const int m0 = blockIdx.y * 128;
    const int n0 = blockIdx.x * 128;
    const int warp_m = (w & 1) * 64;
    const int warp_n = (w >> 1) * 32;

    const __half* srcAh = Ah + (size_t)m0 * K;
    const __half* srcBh = Bh + (size_t)n0 * K;
    const __half* srcAl = SPLIT ? (Al + (size_t)m0 * K) : nullptr;
    const __half* srcBl = SPLIT ? (Bl + (size_t)n0 * K) : nullptr;

    auto load_stage = [&](int s, int k0) {
        uint32_t sdst = sb + s * STAGE_B;
        #pragma unroll
        for (int i = 0; i < 2; i++) {
            int idx = tid + i * 256;        // 0..511
            int row = idx >> 2, ch = idx & 3;
            uint32_t doff = row * ROWB + ch * 16;
            size_t soff = (size_t)row * K + k0 + ch * 8;
            cp16(sdst + doff, srcAh + soff);
            cp16(sdst + TILE_B + doff, srcBh + soff);
            if (SPLIT) {
                cp16(sdst + 2 * TILE_B + doff, srcAl + soff);
                cp16(sdst + 3 * TILE_B + doff, srcBl + soff);
            }
        }
    };

    float acc[4][4][4];
    #pragma unroll
    for (int i = 0; i < 4; i++)
        #pragma unroll
        for (int j = 0; j < 4; j++)
            #pragma unroll
            for (int d = 0; d < 4; d++) acc[i][j][d] = 0.f;

    const int NT = K / BKK;
    load_stage(0, 0);       cp_commit();
    load_stage(1, BKK);     cp_commit();

    const int lm  = lane & 15, kb4 = lane >> 4;
    const int lb  = lane & 7,  kb2 = (lane >> 3) & 1;

    for (int it = 0; it < NT; it++) {
        cp_wait1();
        __syncthreads();

        uint32_t stg = sb + (it % NSTAGEL) * STAGE_B;

        if (!SPLIT) {
            if (it + 2 < NT) { load_stage((it + 2) % NSTAGEL, (it + 2) * BKK); cp_commit(); }
        }

        #pragma unroll
        for (int ks = 0; ks < 2; ks++) {
            uint32_t af[4][4], bf[4][2];
            uint32_t aoff = (warp_m + lm) * ROWB + (ks * 16 + kb4 * 8) * 2;
            uint32_t boff = (warp_n + lb) * ROWB + (ks * 16 + kb2 * 8) * 2;

            #pragma unroll
            for (int mf = 0; mf < 4; mf++)
                ldm_x4(af[mf], stg + aoff + mf * 16 * ROWB);
            #pragma unroll
            for (int nf = 0; nf < 4; nf++)
                ldm_x2(bf[nf], stg + TILE_B + boff + nf * 8 * ROWB);
            #pragma unroll
            for (int mf = 0; mf < 4; mf++)
                #pragma unroll
                for (int nf = 0; nf < 4; nf++)
                    mma_fp16(acc[mf][nf], af[mf], bf[nf]);

            if (SPLIT) {
                #pragma unroll
                for (int nf = 0; nf < 4; nf++)
                    ldm_x2(bf[nf], stg + 3 * TILE_B + boff + nf * 8 * ROWB);
                #pragma unroll
                for (int mf = 0; mf < 4; mf++)
                    #pragma unroll
                    for (int nf = 0; nf < 4; nf++)
                        mma_fp16(acc[mf][nf], af[mf], bf[nf]);

                #pragma unroll
                for (int mf = 0; mf < 4; mf++)
                    ldm_x4(af[mf], stg + 2 * TILE_B + aoff + mf * 16 * ROWB);
                #pragma unroll
                for (int nf = 0; nf < 4; nf++)
                    ldm_x2(bf[nf], stg + TILE_B + boff + nf * 8 * ROWB);
                #pragma unroll
                for (int mf = 0; mf < 4; mf++)
                    #pragma unroll
                    for (int nf = 0; nf < 4; nf++)
                        mma_fp16(acc[mf][nf], af[mf], bf[nf]);
            }
        }
        if (SPLIT) {
            __syncthreads();
            if (it + 2 < NT) { load_stage((it + 2) % NSTAGEL, (it + 2) * BKK); cp_commit(); }
        }
    }

    // ---- epilogue ----
    const int r0 = lane >> 2, c0 = (lane & 3) * 2;
    #pragma unroll
    for (int mf = 0; mf < 4; mf++) {
        #pragma unroll
        for (int nf = 0; nf < 4; nf++) {
            int col = n0 + warp_n + nf * 8 + c0;
            float bv0 = bias[col], bv1 = bias[col + 1];
            #pragma unroll
            for (int h2 = 0; h2 < 2; h2++) {
                int row = m0 + warp_m + mf * 16 + r0 + h2 * 8;
                float v0 = acc[mf][nf][h2 * 2 + 0] + bv0;
                float v1 = acc[mf][nf][h2 * 2 + 1] + bv1;
                if (MODE == 0) {
                    int t = col >> 10, rem = col & 1023;
                    int hh = rem >> 6, d = rem & 63;
                    __half* dst = (t == 0) ? O0 : (t == 1) ? O1 : O2;
                    if (t == 0) {
                        v0 *= 0.18033688011112042f;  // 0.125 * log2(e)
                        v1 *= 0.18033688011112042f;
                    }
                    int b = row >> 11, n = row & 2047;
                    size_t idx = ((size_t)((b << 4) + hh) * SEQ + n) * HEAD_DIM + d;
                    *(__half2*)(dst + idx) = __floats2half2_rn(v0, v1);
                } else if (MODE == 2) {
                    v0 = 0.5f * v0 * (1.0f + erff(v0 * 0.70710678118654752f));
                    v1 = 0.5f * v1 * (1.0f + erff(v1 * 0.70710678118654752f));
                    __half h0, l0, h1, l1;
                    split16(v0, h0, l0);
                    split16(v1, h1, l1);
                    size_t idx = (size_t)row * Nt + col;
                    *(__half2*)(O0 + idx) = __half2(h0, h1);
                    *(__half2*)(O1 + idx) = __half2(l0, l1);
                } else {  // MODE 1 / 3
                    size_t idx = (size_t)row * Nt + col;
                    float2 rr = *(const float2*)(res + idx);
                    float2 o2; o2.x = v0 + rr.x; o2.y = v1 + rr.y;
                    *(float2*)(Cf + idx) = o2;
                }
            }
        }
    }
}

// ================= Flash attention, fp16 mma.sync, exp2 domain =================
// R12 config; ONLY change: l reduced per-thread (fac is quad-uniform) and
// shuffle-reduced ONCE at the end instead of per KV-tile.
#define AT_ROWB 144
#define AT_TILE (64 * AT_ROWB)            // 9216
#define ATTN_SMEM (AT_TILE * 5)           // Q + 2*(K,V) = 46080

__global__ void __launch_bounds__(128, 3) attn_kernel(
    const __half* __restrict__ qb, const __half* __restrict__ kb,
    const __half* __restrict__ vb, __half* __restrict__ ob)
{
    extern __shared__ char smc[];
    uint32_t sb = smem_u32(smc);
    const int tid = threadIdx.x;
    const int w = tid >> 5;
    const int lane = tid & 31;
    const int bh = blockIdx.y;
    const int n0 = blockIdx.x * 64;

    const __half* qg = qb + ((size_t)bh * SEQ + n0) * HEAD_DIM;

    #pragma unroll
    for (int i = 0; i < 4; i++) {
        int idx = tid + i * 128;
        int r = idx >> 3, ch = idx & 7;
        cp16(sb + r * AT_ROWB + ch * 16, qg + (size_t)r * HEAD_DIM + ch * 8);
    }
    cp_commit();

    auto loadKV = [&](int s, int t) {
        const __half* kg = kb + ((size_t)bh * SEQ + t * 64) * HEAD_DIM;
        const __half* vg = vb + ((size_t)bh * SEQ + t * 64) * HEAD_DIM;
        uint32_t ks = sb + AT_TILE + s * 2 * AT_TILE;
        uint32_t vs = ks + AT_TILE;
        #pragma unroll
        for (int i = 0; i < 4; i++) {
            int idx = tid + i * 128;
            int r = idx >> 3, ch = idx & 7;
            cp16(ks + r * AT_ROWB + ch * 16, kg + (size_t)r * HEAD_DIM + ch * 8);
            cp16(vs + r * AT_ROWB + ch * 16, vg + (size_t)r * HEAD_DIM + ch * 8);
        }
    };

    loadKV(0, 0); cp_commit();
    cp_wait1();
    __syncthreads();

    const int lm = lane & 15, kb4 = lane >> 4;
    const int lb = lane & 7,  kb2 = (lane >> 3) & 1;
    uint32_t qf[4][4];
    #pragma unroll
    for (int kf = 0; kf < 4; kf++)
        ldm_x4(qf[kf], sb + (w * 16 + lm) * AT_ROWB + (kf * 16 + kb4 * 8) * 2);

    float of[8][4];
    #pragma unroll
    for (int i = 0; i < 8; i++)
        #pragma unroll
        for (int j = 0; j < 4; j++) of[i][j] = 0.f;
    float m0 = -1e30f, m1 = -1e30f;
    float l0 = 0.f, l1 = 0.f;     // per-thread partials; fac is quad-uniform

    const int NTK = SEQ / 64;
    for (int t = 0; t < NTK; t++) {
        int s = t & 1;
        if (t + 1 < NTK) { loadKV(s ^ 1, t + 1); cp_commit(); }
        if (t + 1 < NTK) cp_wait1(); else cp_wait0();
        __syncthreads();

        uint32_t kbase = sb + AT_TILE + s * 2 * AT_TILE;
        uint32_t vbase = kbase + AT_TILE;

        // ---- S = Q K^T (log2 domain) ----
        float sc[8][4];
        #pragma unroll
        for (int i = 0; i < 8; i++)
            #pragma unroll
            for (int j = 0; j < 4; j++) sc[i][j] = 0.f;
        #pragma unroll
        for (int nf = 0; nf < 8; nf++) {
            uint32_t bf[4][2];
            #pragma unroll
            for (int kf = 0; kf < 4; kf++)
                ldm_x2(bf[kf], kbase + (nf * 8 + lb) * AT_ROWB + (kf * 16 + kb2 * 8) * 2);
            #pragma unroll
            for (int kf = 0; kf < 4; kf++)
                mma_fp16(sc[nf], qf[kf], bf[kf]);
        }

        // ---- online softmax (exp2); l kept per-thread ----
        float mx0 = -1e30f, mx1 = -1e30f;
        #pragma unroll
        for (int nf = 0; nf < 8; nf++) {
            mx0 = fmaxf(mx0, fmaxf(sc[nf][0], sc[nf][1]));
            mx1 = fmaxf(mx1, fmaxf(sc[nf][2], sc[nf][3]));
        }
        mx0 = fmaxf(mx0, __shfl_xor_sync(0xFFFFFFFFu, mx0, 1));
        mx0 = fmaxf(mx0, __shfl_xor_sync(0xFFFFFFFFu, mx0, 2));
        mx1 = fmaxf(mx1, __shfl_xor_sync(0xFFFFFFFFu, mx1, 1));
        mx1 = fmaxf(mx1, __shfl_xor_sync(0xFFFFFFFFu, mx1, 2));
        float mn0 = fmaxf(m0, mx0), mn1 = fmaxf(m1, mx1);
        float fac0 = exp2f(m0 - mn0), fac1 = exp2f(m1 - mn1);
        m0 = mn0; m1 = mn1;
        float ls0 = 0.f, ls1 = 0.f;
        #pragma unroll
        for (int nf = 0; nf < 8; nf++) {
            sc[nf][0] = exp2f(sc[nf][0] - m0);
            sc[nf][1] = exp2f(sc[nf][1] - m0);
            sc[nf][2] = exp2f(sc[nf][2] - m1);
            sc[nf][3] = exp2f(sc[nf][3] - m1);
            ls0 += sc[nf][0] + sc[nf][1];
            ls1 += sc[nf][2] + sc[nf][3];
        }
        l0 = l0 * fac0 + ls0;     // no shuffles here — deferred to the end
        l1 = l1 * fac1 + ls1;
        #pragma unroll
        for (int nf = 0; nf < 8; nf++) {
            of[nf][0] *= fac0; of[nf][1] *= fac0;
            of[nf][2] *= fac1; of[nf][3] *= fac1;
        }

        // ---- P (fp16 A-frags) ----
        uint32_t pa[4][4];
        #pragma unroll
        for (int kf = 0; kf < 4; kf++) {
            pa[kf][0] = pack_h2(sc[2*kf][0],   sc[2*kf][1]);
            pa[kf][1] = pack_h2(sc[2*kf][2],   sc[2*kf][3]);
            pa[kf][2] = pack_h2(sc[2*kf+1][0], sc[2*kf+1][1]);
            pa[kf][3] = pack_h2(sc[2*kf+1][2], sc[2*kf+1][3]);
        }

        // ---- O += P V  (V via trans ldmatrix) ----
        int tl = lane >> 3;
        #pragma unroll
        for (int kf = 0; kf < 4; kf++) {
            #pragma unroll
            for (int nb = 0; nb < 4; nb++) {
                uint32_t vf[4];
                int row = kf * 16 + (tl & 1) * 8 + (lane & 7);
                int col = nb * 16 + (tl >> 1) * 8;
                ldm_x4t(vf, vbase + row * AT_ROWB + col * 2);
                mma_fp16(of[2*nb],     pa[kf], vf);
                mma_fp16(of[2*nb + 1], pa[kf], vf + 2);
            }
        }
        __syncthreads();
    }

    // ---- single final l reduction across the 4 threads sharing each row ----
    l0 += __shfl_xor_sync(0xFFFFFFFFu, l0, 1);
    l0 += __shfl_xor_sync(0xFFFFFFFFu, l0, 2);
    l1 += __shfl_xor_sync(0xFFFFFFFFu, l1, 1);
    l1 += __shfl_xor_sync(0xFFFFFFFFu, l1, 2);

    // ---- epilogue ----
    float inv0 = 1.0f / l0, inv1 = 1.0f / l1;
    int b = bh >> 4, hh = bh & 15;
    int r0g = n0 + w * 16 + (lane >> 2);
    size_t tok0 = (size_t)(b * SEQ + r0g);
    size_t tok1 = tok0 + 8;
    int colb = hh * HEAD_DIM + 2 * (lane & 3);
    #pragma unroll
    for (int nf = 0; nf < 8; nf++) {
        int col = colb + nf * 8;
        *(__half2*)(ob + tok0 * DIM + col) = __floats2half2_rn(of[nf][0] * inv0, of[nf][1] * inv0);
        *(__half2*)(ob + tok1 * DIM + col) = __floats2half2_rn(of[nf][2] * inv1, of[nf][3] * inv1);
    }
}

// ================= launch =================
extern "C" void kernel_launch(void* const* d_in, const int* in_sizes, int n_in,
                              void* d_out, int out_size)
{
    (void)in_sizes; (void)n_in; (void)out_size;
    const float* x      = (const float*)d_in[0];
    const float* ln1_g  = (const float*)d_in[1];
    const float* ln1_b  = (const float*)d_in[2];
    const float* ln2_g  = (const float*)d_in[3];
    const float* ln2_b  = (const float*)d_in[4];
    const float* w_qkv  = (const float*)d_in[5];
    const float* b_qkv  = (const float*)d_in[6];
    const float* w_proj = (const float*)d_in[7];
    const float* b_proj = (const float*)d_in[8];
    const float* w_fc1  = (const float*)d_in[9];
    const float* b_fc1  = (const float*)d_in[10];
    const float* w_fc2  = (const float*)d_in[11];
    const float* b_fc2  = (const float*)d_in[12];
    float* out = (float*)d_out;

    __half *a, *ah, *al, *q, *k, *v, *o, *f1h, *f1l;
    __half *wq, *wp, *w1h, *w1l, *w2h, *w2l;
    cudaGetSymbolAddress((void**)&a,   g_a);
    cudaGetSymbolAddress((void**)&ah,  g_ah);
    cudaGetSymbolAddress((void**)&al,  g_al);
    cudaGetSymbolAddress((void**)&q,   g_q);
    cudaGetSymbolAddress((void**)&k,   g_k);
    cudaGetSymbolAddress((void**)&v,   g_v);
    cudaGetSymbolAddress((void**)&o,   g_o);
    cudaGetSymbolAddress((void**)&f1h, g_f1h);
    cudaGetSymbolAddress((void**)&f1l, g_f1l);
    cudaGetSymbolAddress((void**)&wq,  g_wqkvT);
    cudaGetSymbolAddress((void**)&wp,  g_wprojT);
    cudaGetSymbolAddress((void**)&w1h, g_wfc1T_h);
    cudaGetSymbolAddress((void**)&w1l, g_wfc1T_l);
    cudaGetSymbolAddress((void**)&w2h, g_wfc2T_h);
    cudaGetSymbolAddress((void**)&w2l, g_wfc2T_l);

    const int SMEM_SINGLE = 3 * 2 * TILE_B;   // 61440 (3 stages)
    const int SMEM_SPLIT  = 2 * 4 * TILE_B;   // 81920 (2 stages)
    cudaFuncSetAttribute(attn_kernel, cudaFuncAttributeMaxDynamicSharedMemorySize, ATTN_SMEM);
    cudaFuncSetAttribute((gemm_tc<0,0>), cudaFuncAttributeMaxDynamicSharedMemorySize, SMEM_SINGLE);
    cudaFuncSetAttribute((gemm_tc<1,0>), cudaFuncAttributeMaxDynamicSharedMemorySize, SMEM_SINGLE);
    cudaFuncSetAttribute((gemm_tc<2,1>), cudaFuncAttributeMaxDynamicSharedMemorySize, SMEM_SPLIT);
    cudaFuncSetAttribute((gemm_tc<3,1>), cudaFuncAttributeMaxDynamicSharedMemorySize, SMEM_SPLIT);

    // ---- side stream for all weight transposes (captured event fork-join) ----
    cudaStream_t s1;
    cudaStreamCreateWithFlags(&s1, cudaStreamNonBlocking);
    cudaEvent_t eFork, eQkvT, eJoin;
    cudaEventCreateWithFlags(&eFork, cudaEventDisableTiming);
    cudaEventCreateWithFlags(&eQkvT, cudaEventDisableTiming);
    cudaEventCreateWithFlags(&eJoin, cudaEventDisableTiming);

    dim3 tb(16, 16);
    cudaEventRecord(eFork, 0);
    cudaStreamWaitEvent(s1, eFork, 0);
    wT_kernel<0><<<dim3(3 * DIM / 32, DIM / 32), tb, 0, s1>>>(w_qkv, wq, nullptr, DIM, 3 * DIM);
    cudaEventRecord(eQkvT, s1);
    wT_kernel<0><<<dim3(DIM / 32, DIM / 32), tb, 0, s1>>>(w_proj, wp, nullptr, DIM, DIM);
    wT_kernel<1><<<dim3(HIDDEN / 32, DIM / 32), tb, 0, s1>>>(w_fc1, w1h, w1l, DIM, HIDDEN);
    wT_kernel<1><<<dim3(DIM / 32, HIDDEN / 32), tb, 0, s1>>>(w_fc2, w2h, w2l, HIDDEN, DIM);
    cudaEventRecord(eJoin, s1);

    // main stream
    ln_kernel<0><<<TOKENS, 256>>>(x, ln1_g, ln1_b, a, nullptr);
    cudaStreamWaitEvent(0, eQkvT, 0);
    gemm_tc<0,0><<<dim3(3 * DIM / 128, TOKENS / 128), 256, SMEM_SINGLE>>>(
        a, nullptr, wq, nullptr, b_qkv, nullptr, nullptr, q, k, v, 3 * DIM, DIM);
    attn_kernel<<<dim3(SEQ / 64, BATCH * HEADS), 128, ATTN_SMEM>>>(q, k, v, o);
    cudaStreamWaitEvent(0, eJoin, 0);
    gemm_tc<1,0><<<dim3(DIM / 128, TOKENS / 128), 256, SMEM_SINGLE>>>(
        o, nullptr, wp, nullptr, b_proj, x, out, nullptr, nullptr, nullptr, DIM, DIM);
    ln_kernel<1><<<TOKENS, 256>>>(out, ln2_g, ln2_b, ah, al);
    gemm_tc<2,1><<<dim3(HIDDEN / 128, TOKENS / 128), 256, SMEM_SPLIT>>>(
        ah, al, w1h, w1l, b_fc1, nullptr, nullptr, f1h, f1l, nullptr, HIDDEN, DIM);
    gemm_tc<3,1><<<dim3(DIM / 128, TOKENS / 128), 256, SMEM_SPLIT>>>(
        f1h, f1l, w2h, w2l, b_fc2, out, out, nullptr, nullptr, nullptr, DIM, HIDDEN);
}

// round 15
// speedup vs baseline: 1.5749x; 1.0393x over previous
#include <cuda_runtime.h>
#include <cuda_fp16.h>
#include <math.h>
#include <stdint.h>

#define DIM 1024
#define HEADS 16
#define HEAD_DIM 64
#define HIDDEN 4096
#define BATCH 4
#define SEQ 2048
#define TOKENS (BATCH * SEQ)   // 8192
#define EPS 1e-5f

// ================= scratch (device globals) =================
__device__ __half g_a[TOKENS * DIM];          // LN1 out fp16 (single)
__device__ __half g_ah[TOKENS * DIM];         // LN2 out split hi
__device__ __half g_al[TOKENS * DIM];         // LN2 out split lo
__device__ __half g_q[TOKENS * DIM];          // [b*h][n][64], q pre-scaled 0.125*log2e
__device__ __half g_k[TOKENS * DIM];
__device__ __half g_v[TOKENS * DIM];
__device__ __half g_o[TOKENS * DIM];          // attn out [token][h*64+d]
__device__ __half g_f1h[TOKENS * HIDDEN];     // fc1+gelu out split
__device__ __half g_f1l[TOKENS * HIDDEN];
__device__ __half g_wqkvT[3 * DIM * DIM];     // [N,K] single
__device__ __half g_wprojT[DIM * DIM];        // single
__device__ __half g_wfc1T_h[HIDDEN * DIM];    // split
__device__ __half g_wfc1T_l[HIDDEN * DIM];
__device__ __half g_wfc2T_h[DIM * HIDDEN];
__device__ __half g_wfc2T_l[DIM * HIDDEN];

// ================= PTX helpers (plain sm_80+ PTX) =================
__device__ __forceinline__ uint32_t smem_u32(const void* p) {
    return (uint32_t)__cvta_generic_to_shared(p);
}
__device__ __forceinline__ void cp16(uint32_t dst, const void* src) {
    asm volatile("cp.async.cg.shared.global [%0], [%1], 16;" :: "r"(dst), "l"(src) : "memory");
}
__device__ __forceinline__ void cp_commit() {
    asm volatile("cp.async.commit_group;" ::: "memory");
}
__device__ __forceinline__ void cp_wait1() {
    asm volatile("cp.async.wait_group 1;" ::: "memory");
}
__device__ __forceinline__ void cp_wait0() {
    asm volatile("cp.async.wait_group 0;" ::: "memory");
}
__device__ __forceinline__ void ldm_x4(uint32_t* r, uint32_t addr) {
    asm volatile("ldmatrix.sync.aligned.m8n8.x4.shared.b16 {%0,%1,%2,%3}, [%4];"
                 : "=r"(r[0]), "=r"(r[1]), "=r"(r[2]), "=r"(r[3]) : "r"(addr));
}
__device__ __forceinline__ void ldm_x4t(uint32_t* r, uint32_t addr) {
    asm volatile("ldmatrix.sync.aligned.m8n8.x4.trans.shared.b16 {%0,%1,%2,%3}, [%4];"
                 : "=r"(r[0]), "=r"(r[1]), "=r"(r[2]), "=r"(r[3]) : "r"(addr));
}
__device__ __forceinline__ void mma_fp16(float* d, const uint32_t* a, const uint32_t* b) {
    asm volatile(
        "mma.sync.aligned.m16n8k16.row.col.f32.f16.f16.f32 "
        "{%0,%1,%2,%3}, {%4,%5,%6,%7}, {%8,%9}, {%0,%1,%2,%3};"
        : "+f"(d[0]), "+f"(d[1]), "+f"(d[2]), "+f"(d[3])
        : "r"(a[0]), "r"(a[1]), "r"(a[2]), "r"(a[3]), "r"(b[0]), "r"(b[1]));
}
__device__ __forceinline__ uint32_t pack_h2(float a, float b) {
    __half2 h = __floats2half2_rn(a, b);
    return *(uint32_t*)&h;
}
__device__ __forceinline__ void split16(float v, __half& h, __half& l) {
    h = __float2half_rn(v);
    l = __float2half_rn(v - __half2float(h));
}

// ================= LayerNorm =================
template<int SPLIT>
__global__ void ln_kernel(const float* __restrict__ x,
                          const float* __restrict__ g,
                          const float* __restrict__ b,
                          __half* __restrict__ o0, __half* __restrict__ o1)
{
    int row = blockIdx.x;
    const float4* xr = (const float4*)(x + (size_t)row * DIM);
    int tid = threadIdx.x;
    float4 v = xr[tid];
    float s  = v.x + v.y + v.z + v.w;
    float ss = v.x*v.x + v.y*v.y + v.z*v.z + v.w*v.w;
    for (int o = 16; o > 0; o >>= 1) {
        s  += __shfl_down_sync(0xFFFFFFFFu, s,  o);
        ss += __shfl_down_sync(0xFFFFFFFFu, ss, o);
    }
    __shared__ float red_s[8], red_ss[8];
    int wid = tid >> 5, lid = tid & 31;
    if (lid == 0) { red_s[wid] = s; red_ss[wid] = ss; }
    __syncthreads();
    __shared__ float sh_mu, sh_rstd;
    if (tid == 0) {
        float ts = 0.f, tss = 0.f;
        #pragma unroll
        for (int i = 0; i < 8; i++) { ts += red_s[i]; tss += red_ss[i]; }
        float mu  = ts * (1.0f / DIM);
        float var = tss * (1.0f / DIM) - mu * mu;
        sh_mu = mu; sh_rstd = rsqrtf(var + EPS);
    }
    __syncthreads();
    float mu = sh_mu, rstd = sh_rstd;

    int c = tid * 4;
    float4 gg = *(const float4*)(g + c);
    float4 bb = *(const float4*)(b + c);
    float y[4];
    y[0] = (v.x - mu) * rstd * gg.x + bb.x;
    y[1] = (v.y - mu) * rstd * gg.y + bb.y;
    y[2] = (v.z - mu) * rstd * gg.z + bb.z;
    y[3] = (v.w - mu) * rstd * gg.w + bb.w;
    size_t base = (size_t)row * DIM + c;
    #pragma unroll
    for (int i = 0; i < 4; i += 2) {
        if (SPLIT) {
            __half h0, l0, h1, l1;
            split16(y[i], h0, l0);
            split16(y[i+1], h1, l1);
            *(__half2*)(o0 + base + i) = __half2(h0, h1);
            *(__half2*)(o1 + base + i) = __half2(l0, l1);
        } else {
            *(__half2*)(o0 + base + i) = __floats2half2_rn(y[i], y[i+1]);
        }
    }
}

// ========== weight transpose: w[K,N] f32 -> [N,K] fp16 (single or split) ==========
template<int SPLIT>
__global__ void wT_kernel(const float* __restrict__ w,
                          __half* __restrict__ o0, __half* __restrict__ o1,
                          int K, int N)
{
    __shared__ float t[32][33];
    int n0 = blockIdx.x * 32, k0 = blockIdx.y * 32;
    int tx = threadIdx.x;   // 0..15
    int ty = threadIdx.y;   // 0..15
    #pragma unroll
    for (int r = 0; r < 2; r++) {
        int kk = ty + r * 16;
        float2 v = *(const float2*)(w + (size_t)(k0 + kk) * N + n0 + tx * 2);
        t[kk][tx * 2]     = v.x;
        t[kk][tx * 2 + 1] = v.y;
    }
    __syncthreads();
    #pragma unroll
    for (int r = 0; r < 2; r++) {
        int nn = ty + r * 16;
        float v0 = t[tx * 2][nn];
        float v1 = t[tx * 2 + 1][nn];
        size_t idx = (size_t)(n0 + nn) * K + k0 + tx * 2;
        if (SPLIT) {
            __half h0, l0, h1, l1;
            split16(v0, h0, l0);
            split16(v1, h1, l1);
            *(__half2*)(o0 + idx) = __half2(h0, h1);
            *(__half2*)(o1 + idx) = __half2(l0, l1);
        } else {
            *(__half2*)(o0 + idx) = __floats2half2_rn(v0, v1);
        }
    }
}

// ================= fp16 mma.sync GEMM (R12 config; B-frags via ldm_x4) ========
// MODE 0: single, +bias, scatter QKV fp16 (q scaled 0.125*log2e)
// MODE 1: single, +bias+res -> f32
// MODE 2: split,  +bias, exact GELU -> split fp16 (O0=hi, O1=lo)
// MODE 3: split,  +bias+res -> f32
#define ROWB   80
#define TILE_B (128 * ROWB)            // 10240
#define BKK 32

template<int MODE, int SPLIT>
__global__ void __launch_bounds__(256, 2) gemm_tc(
    const __half* __restrict__ Ah, const __half* __restrict__ Al,
    const __half* __restrict__ Bh, const __half* __restrict__ Bl,
    const float* __restrict__ bias, const float* __restrict__ res,
    float* __restrict__ Cf, __half* __restrict__ O0,
    __half* __restrict__ O1, __half* __restrict__ O2,
    int Nt, int K)
{
    const int NTILES = SPLIT ? 4 : 2;
    const int STAGE_B = NTILES * TILE_B;
    const int NSTAGEL = SPLIT ? 2 : 3;     // split: 2 stages so 2 CTAs/SM fit
    extern __shared__ char smem[];
    uint32_t sb = smem_u32(smem);
    const int tid = threadIdx.x;
    const int w = tid >> 5;
    const int lane = tid & 31;
    const int m0 = blockIdx.y * 128;
    const int n0 = blockIdx.x * 128;
    const int warp_m = (w & 1) * 64;
    const int warp_n = (w >> 1) * 32;

    const __half* srcAh = Ah + (size_t)m0 * K;
    const __half* srcBh = Bh + (size_t)n0 * K;
    const __half* srcAl = SPLIT ? (Al + (size_t)m0 * K) : nullptr;
    const __half* srcBl = SPLIT ? (Bl + (size_t)n0 * K) : nullptr;

    auto load_stage = [&](int s, int k0) {
        uint32_t sdst = sb + s * STAGE_B;
        #pragma unroll
        for (int i = 0; i < 2; i++) {
            int idx = tid + i * 256;        // 0..511
            int row = idx >> 2, ch = idx & 3;
            uint32_t doff = row * ROWB + ch * 16;
            size_t soff = (size_t)row * K + k0 + ch * 8;
            cp16(sdst + doff, srcAh + soff);
            cp16(sdst + TILE_B + doff, srcBh + soff);
            if (SPLIT) {
                cp16(sdst + 2 * TILE_B + doff, srcAl + soff);
                cp16(sdst + 3 * TILE_B + doff, srcBl + soff);
            }
        }
    };

    float acc[4][4][4];
    #pragma unroll
    for (int i = 0; i < 4; i++)
        #pragma unroll
        for (int j = 0; j < 4; j++)
            #pragma unroll
            for (int d = 0; d < 4; d++) acc[i][j][d] = 0.f;

    const int NT = K / BKK;
    load_stage(0, 0);       cp_commit();
    load_stage(1, BKK);     cp_commit();

    const int lm  = lane & 15, kb4 = lane >> 4;
    // B-frag ldm_x4 lane map: matrix = lane>>3; nf-pair row half = (lane>>4);
    // k-chunk = (lane>>3)&1. One x4 loads bf[nf] and bf[nf+1].
    const int brow4 = (lane >> 4) * 8 + (lane & 7);
    const int bchk4 = ((lane >> 3) & 1) * 8;

    for (int it = 0; it < NT; it++) {
        cp_wait1();
        __syncthreads();

        uint32_t stg = sb + (it % NSTAGEL) * STAGE_B;

        if (!SPLIT) {
            if (it + 2 < NT) { load_stage((it + 2) % NSTAGEL, (it + 2) * BKK); cp_commit(); }
        }

        #pragma unroll
        for (int ks = 0; ks < 2; ks++) {
            uint32_t af[4][4], bf[4][2];
            uint32_t aoff = (warp_m + lm) * ROWB + (ks * 16 + kb4 * 8) * 2;
            uint32_t boff4 = (warp_n + brow4) * ROWB + (ks * 16 + bchk4) * 2;

            #pragma unroll
            for (int mf = 0; mf < 4; mf++)
                ldm_x4(af[mf], stg + aoff + mf * 16 * ROWB);
            #pragma unroll
            for (int p = 0; p < 2; p++)
                ldm_x4(&bf[2*p][0], stg + TILE_B + boff4 + p * 16 * ROWB);
            #pragma unroll
            for (int mf = 0; mf < 4; mf++)
                #pragma unroll
                for (int nf = 0; nf < 4; nf++)
                    mma_fp16(acc[mf][nf], af[mf], bf[nf]);

            if (SPLIT) {
                #pragma unroll
                for (int p = 0; p < 2; p++)
                    ldm_x4(&bf[2*p][0], stg + 3 * TILE_B + boff4 + p * 16 * ROWB);
                #pragma unroll
                for (int mf = 0; mf < 4; mf++)
                    #pragma unroll
                    for (int nf = 0; nf < 4; nf++)
                        mma_fp16(acc[mf][nf], af[mf], bf[nf]);

                #pragma unroll
                for (int mf = 0; mf < 4; mf++)
                    ldm_x4(af[mf], stg + 2 * TILE_B + aoff + mf * 16 * ROWB);
                #pragma unroll
                for (int p = 0; p < 2; p++)
                    ldm_x4(&bf[2*p][0], stg + TILE_B + boff4 + p * 16 * ROWB);
                #pragma unroll
                for (int mf = 0; mf < 4; mf++)
                    #pragma unroll
                    for (int nf = 0; nf < 4; nf++)
                        mma_fp16(acc[mf][nf], af[mf], bf[nf]);
            }
        }
        if (SPLIT) {
            __syncthreads();
            if (it + 2 < NT) { load_stage((it + 2) % NSTAGEL, (it + 2) * BKK); cp_commit(); }
        }
    }

    // ---- epilogue ----
    const int r0 = lane >> 2, c0 = (lane & 3) * 2;
    #pragma unroll
    for (int mf = 0; mf < 4; mf++) {
        #pragma unroll
        for (int nf = 0; nf < 4; nf++) {
            int col = n0 + warp_n + nf * 8 + c0;
            float bv0 = bias[col], bv1 = bias[col + 1];
            #pragma unroll
            for (int h2 = 0; h2 < 2; h2++) {
                int row = m0 + warp_m + mf * 16 + r0 + h2 * 8;
                float v0 = acc[mf][nf][h2 * 2 + 0] + bv0;
                float v1 = acc[mf][nf][h2 * 2 + 1] + bv1;
                if (MODE == 0) {
                    int t = col >> 10, rem = col & 1023;
                    int hh = rem >> 6, d = rem & 63;
                    __half* dst = (t == 0) ? O0 : (t == 1) ? O1 : O2;
                    if (t == 0) {
                        v0 *= 0.18033688011112042f;  // 0.125 * log2(e)
                        v1 *= 0.18033688011112042f;
                    }
                    int b = row >> 11, n = row & 2047;
                    size_t idx = ((size_t)((b << 4) + hh) * SEQ + n) * HEAD_DIM + d;
                    *(__half2*)(dst + idx) = __floats2half2_rn(v0, v1);
                } else if (MODE == 2) {
                    v0 = 0.5f * v0 * (1.0f + erff(v0 * 0.70710678118654752f));
                    v1 = 0.5f * v1 * (1.0f + erff(v1 * 0.70710678118654752f));
                    __half h0, l0, h1, l1;
                    split16(v0, h0, l0);
                    split16(v1, h1, l1);
                    size_t idx = (size_t)row * Nt + col;
                    *(__half2*)(O0 + idx) = __half2(h0, h1);
                    *(__half2*)(O1 + idx) = __half2(l0, l1);
                } else {  // MODE 1 / 3
                    size_t idx = (size_t)row * Nt + col;
                    float2 rr = *(const float2*)(res + idx);
                    float2 o2; o2.x = v0 + rr.x; o2.y = v1 + rr.y;
                    *(float2*)(Cf + idx) = o2;
                }
            }
        }
    }
}

// ================= Flash attention, fp16 mma.sync, exp2 domain =================
// R12 config + deferred l-reduction + K-frags via ldm_x4 (kf pairs).
#define AT_ROWB 144
#define AT_TILE (64 * AT_ROWB)            // 9216
#define ATTN_SMEM (AT_TILE * 5)           // Q + 2*(K,V) = 46080

__global__ void __launch_bounds__(128, 3) attn_kernel(
    const __half* __restrict__ qb, const __half* __restrict__ kb,
    const __half* __restrict__ vb, __half* __restrict__ ob)
{
    extern __shared__ char smc[];
    uint32_t sb = smem_u32(smc);
    const int tid = threadIdx.x;
    const int w = tid >> 5;
    const int lane = tid & 31;
    const int bh = blockIdx.y;
    const int n0 = blockIdx.x * 64;

    const __half* qg = qb + ((size_t)bh * SEQ + n0) * HEAD_DIM;

    #pragma unroll
    for (int i = 0; i < 4; i++) {
        int idx = tid + i * 128;
        int r = idx >> 3, ch = idx & 7;
        cp16(sb + r * AT_ROWB + ch * 16, qg + (size_t)r * HEAD_DIM + ch * 8);
    }
    cp_commit();

    auto loadKV = [&](int s, int t) {
        const __half* kg = kb + ((size_t)bh * SEQ + t * 64) * HEAD_DIM;
        const __half* vg = vb + ((size_t)bh * SEQ + t * 64) * HEAD_DIM;
        uint32_t ks = sb + AT_TILE + s * 2 * AT_TILE;
        uint32_t vs = ks + AT_TILE;
        #pragma unroll
        for (int i = 0; i < 4; i++) {
            int idx = tid + i * 128;
            int r = idx >> 3, ch = idx & 7;
            cp16(ks + r * AT_ROWB + ch * 16, kg + (size_t)r * HEAD_DIM + ch * 8);
            cp16(vs + r * AT_ROWB + ch * 16, vg + (size_t)r * HEAD_DIM + ch * 8);
        }
    };

    loadKV(0, 0); cp_commit();
    cp_wait1();
    __syncthreads();

    const int lm = lane & 15, kb4 = lane >> 4;
    uint32_t qf[4][4];
    #pragma unroll
    for (int kf = 0; kf < 4; kf++)
        ldm_x4(qf[kf], sb + (w * 16 + lm) * AT_ROWB + (kf * 16 + kb4 * 8) * 2);

    // K-frag ldm_x4 lane map: matrix = lane>>3 -> (kf-pair local, k-chunk);
    // row = nf*8 + (lane&7); byte offset within kf-pair = (lane>>3)*16.
    const int krow4 = lane & 7;
    const int kchk4 = (lane >> 3) * 16;

    float of[8][4];
    #pragma unroll
    for (int i = 0; i < 8; i++)
        #pragma unroll
        for (int j = 0; j < 4; j++) of[i][j] = 0.f;
    float m0 = -1e30f, m1 = -1e30f;
    float l0 = 0.f, l1 = 0.f;     // per-thread partials; fac is quad-uniform

    const int NTK = SEQ / 64;
    for (int t = 0; t < NTK; t++) {
        int s = t & 1;
        if (t + 1 < NTK) { loadKV(s ^ 1, t + 1); cp_commit(); }
        if (t + 1 < NTK) cp_wait1(); else cp_wait0();
        __syncthreads();

        uint32_t kbase = sb + AT_TILE + s * 2 * AT_TILE;
        uint32_t vbase = kbase + AT_TILE;

        // ---- S = Q K^T (log2 domain) ----
        float sc[8][4];
        #pragma unroll
        for (int i = 0; i < 8; i++)
            #pragma unroll
            for (int j = 0; j < 4; j++) sc[i][j] = 0.f;
        #pragma unroll
        for (int nf = 0; nf < 8; nf++) {
            uint32_t bf[4][2];
            uint32_t kat = kbase + (nf * 8 + krow4) * AT_ROWB + kchk4;
            #pragma unroll
            for (int p = 0; p < 2; p++)
                ldm_x4(&bf[2*p][0], kat + p * 64);
            #pragma unroll
            for (int kf = 0; kf < 4; kf++)
                mma_fp16(sc[nf], qf[kf], bf[kf]);
        }

        // ---- online softmax (exp2); l kept per-thread ----
        float mx0 = -1e30f, mx1 = -1e30f;
        #pragma unroll
        for (int nf = 0; nf < 8; nf++) {
            mx0 = fmaxf(mx0, fmaxf(sc[nf][0], sc[nf][1]));
            mx1 = fmaxf(mx1, fmaxf(sc[nf][2], sc[nf][3]));
        }
        mx0 = fmaxf(mx0, __shfl_xor_sync(0xFFFFFFFFu, mx0, 1));
        mx0 = fmaxf(mx0, __shfl_xor_sync(0xFFFFFFFFu, mx0, 2));
        mx1 = fmaxf(mx1, __shfl_xor_sync(0xFFFFFFFFu, mx1, 1));
        mx1 = fmaxf(mx1, __shfl_xor_sync(0xFFFFFFFFu, mx1, 2));
        float mn0 = fmaxf(m0, mx0), mn1 = fmaxf(m1, mx1);
        float fac0 = exp2f(m0 - mn0), fac1 = exp2f(m1 - mn1);
        m0 = mn0; m1 = mn1;
        float ls0 = 0.f, ls1 = 0.f;
        #pragma unroll
        for (int nf = 0; nf < 8; nf++) {
            sc[nf][0] = exp2f(sc[nf][0] - m0);
            sc[nf][1] = exp2f(sc[nf][1] - m0);
            sc[nf][2] = exp2f(sc[nf][2] - m1);
            sc[nf][3] = exp2f(sc[nf][3] - m1);
            ls0 += sc[nf][0] + sc[nf][1];
            ls1 += sc[nf][2] + sc[nf][3];
        }
        l0 = l0 * fac0 + ls0;     // shuffles deferred to the end
        l1 = l1 * fac1 + ls1;
        #pragma unroll
        for (int nf = 0; nf < 8; nf++) {
            of[nf][0] *= fac0; of[nf][1] *= fac0;
            of[nf][2] *= fac1; of[nf][3] *= fac1;
        }

        // ---- P (fp16 A-frags) ----
        uint32_t pa[4][4];
        #pragma unroll
        for (int kf = 0; kf < 4; kf++) {
            pa[kf][0] = pack_h2(sc[2*kf][0],   sc[2*kf][1]);
            pa[kf][1] = pack_h2(sc[2*kf][2],   sc[2*kf][3]);
            pa[kf][2] = pack_h2(sc[2*kf+1][0], sc[2*kf+1][1]);
            pa[kf][3] = pack_h2(sc[2*kf+1][2], sc[2*kf+1][3]);
        }

        // ---- O += P V  (V via trans ldmatrix) ----
        int tl = lane >> 3;
        #pragma unroll
        for (int kf = 0; kf < 4; kf++) {
            #pragma unroll
            for (int nb = 0; nb < 4; nb++) {
                uint32_t vf[4];
                int row = kf * 16 + (tl & 1) * 8 + (lane & 7);
                int col = nb * 16 + (tl >> 1) * 8;
                ldm_x4t(vf, vbase + row * AT_ROWB + col * 2);
                mma_fp16(of[2*nb],     pa[kf], vf);
                mma_fp16(of[2*nb + 1], pa[kf], vf + 2);
            }
        }
        __syncthreads();
    }

    // ---- single final l reduction across the 4 threads sharing each row ----
    l0 += __shfl_xor_sync(0xFFFFFFFFu, l0, 1);
    l0 += __shfl_xor_sync(0xFFFFFFFFu, l0, 2);
    l1 += __shfl_xor_sync(0xFFFFFFFFu, l1, 1);
    l1 += __shfl_xor_sync(0xFFFFFFFFu, l1, 2);

    // ---- epilogue ----
    float inv0 = 1.0f / l0, inv1 = 1.0f / l1;
    int b = bh >> 4, hh = bh & 15;
    int r0g = n0 + w * 16 + (lane >> 2);
    size_t tok0 = (size_t)(b * SEQ + r0g);
    size_t tok1 = tok0 + 8;
    int colb = hh * HEAD_DIM + 2 * (lane & 3);
    #pragma unroll
    for (int nf = 0; nf < 8; nf++) {
        int col = colb + nf * 8;
        *(__half2*)(ob + tok0 * DIM + col) = __floats2half2_rn(of[nf][0] * inv0, of[nf][1] * inv0);
        *(__half2*)(ob + tok1 * DIM + col) = __floats2half2_rn(of[nf][2] * inv1, of[nf][3] * inv1);
    }
}

// ================= launch =================
extern "C" void kernel_launch(void* const* d_in, const int* in_sizes, int n_in,
                              void* d_out, int out_size)
{
    (void)in_sizes; (void)n_in; (void)out_size;
    const float* x      = (const float*)d_in[0];
    const float* ln1_g  = (const float*)d_in[1];
    const float* ln1_b  = (const float*)d_in[2];
    const float* ln2_g  = (const float*)d_in[3];
    const float* ln2_b  = (const float*)d_in[4];
    const float* w_qkv  = (const float*)d_in[5];
    const float* b_qkv  = (const float*)d_in[6];
    const float* w_proj = (const float*)d_in[7];
    const float* b_proj = (const float*)d_in[8];
    const float* w_fc1  = (const float*)d_in[9];
    const float* b_fc1  = (const float*)d_in[10];
    const float* w_fc2  = (const float*)d_in[11];
    const float* b_fc2  = (const float*)d_in[12];
    float* out = (float*)d_out;

    __half *a, *ah, *al, *q, *k, *v, *o, *f1h, *f1l;
    __half *wq, *wp, *w1h, *w1l, *w2h, *w2l;
    cudaGetSymbolAddress((void**)&a,   g_a);
    cudaGetSymbolAddress((void**)&ah,  g_ah);
    cudaGetSymbolAddress((void**)&al,  g_al);
    cudaGetSymbolAddress((void**)&q,   g_q);
    cudaGetSymbolAddress((void**)&k,   g_k);
    cudaGetSymbolAddress((void**)&v,   g_v);
    cudaGetSymbolAddress((void**)&o,   g_o);
    cudaGetSymbolAddress((void**)&f1h, g_f1h);
    cudaGetSymbolAddress((void**)&f1l, g_f1l);
    cudaGetSymbolAddress((void**)&wq,  g_wqkvT);
    cudaGetSymbolAddress((void**)&wp,  g_wprojT);
    cudaGetSymbolAddress((void**)&w1h, g_wfc1T_h);
    cudaGetSymbolAddress((void**)&w1l, g_wfc1T_l);
    cudaGetSymbolAddress((void**)&w2h, g_wfc2T_h);
    cudaGetSymbolAddress((void**)&w2l, g_wfc2T_l);

    const int SMEM_SINGLE = 3 * 2 * TILE_B;   // 61440 (3 stages)
    const int SMEM_SPLIT  = 2 * 4 * TILE_B;   // 81920 (2 stages)
    cudaFuncSetAttribute(attn_kernel, cudaFuncAttributeMaxDynamicSharedMemorySize, ATTN_SMEM);
    cudaFuncSetAttribute((gemm_tc<0,0>), cudaFuncAttributeMaxDynamicSharedMemorySize, SMEM_SINGLE);
    cudaFuncSetAttribute((gemm_tc<1,0>), cudaFuncAttributeMaxDynamicSharedMemorySize, SMEM_SINGLE);
    cudaFuncSetAttribute((gemm_tc<2,1>), cudaFuncAttributeMaxDynamicSharedMemorySize, SMEM_SPLIT);
    cudaFuncSetAttribute((gemm_tc<3,1>), cudaFuncAttributeMaxDynamicSharedMemorySize, SMEM_SPLIT);

    // ---- side stream for all weight transposes (captured event fork-join) ----
    cudaStream_t s1;
    cudaStreamCreateWithFlags(&s1, cudaStreamNonBlocking);
    cudaEvent_t eFork, eQkvT, eJoin;
    cudaEventCreateWithFlags(&eFork, cudaEventDisableTiming);
    cudaEventCreateWithFlags(&eQkvT, cudaEventDisableTiming);
    cudaEventCreateWithFlags(&eJoin, cudaEventDisableTiming);

    dim3 tb(16, 16);
    cudaEventRecord(eFork, 0);
    cudaStreamWaitEvent(s1, eFork, 0);
    wT_kernel<0><<<dim3(3 * DIM / 32, DIM / 32), tb, 0, s1>>>(w_qkv, wq, nullptr, DIM, 3 * DIM);
    cudaEventRecord(eQkvT, s1);
    wT_kernel<0><<<dim3(DIM / 32, DIM / 32), tb, 0, s1>>>(w_proj, wp, nullptr, DIM, DIM);
    wT_kernel<1><<<dim3(HIDDEN / 32, DIM / 32), tb, 0, s1>>>(w_fc1, w1h, w1l, DIM, HIDDEN);
    wT_kernel<1><<<dim3(DIM / 32, HIDDEN / 32), tb, 0, s1>>>(w_fc2, w2h, w2l, HIDDEN, DIM);
    cudaEventRecord(eJoin, s1);

    // main stream
    ln_kernel<0><<<TOKENS, 256>>>(x, ln1_g, ln1_b, a, nullptr);
    cudaStreamWaitEvent(0, eQkvT, 0);
    gemm_tc<0,0><<<dim3(3 * DIM / 128, TOKENS / 128), 256, SMEM_SINGLE>>>(
        a, nullptr, wq, nullptr, b_qkv, nullptr, nullptr, q, k, v, 3 * DIM, DIM);
    attn_kernel<<<dim3(SEQ / 64, BATCH * HEADS), 128, ATTN_SMEM>>>(q, k, v, o);
    cudaStreamWaitEvent(0, eJoin, 0);
    gemm_tc<1,0><<<dim3(DIM / 128, TOKENS / 128), 256, SMEM_SINGLE>>>(
        o, nullptr, wp, nullptr, b_proj, x, out, nullptr, nullptr, nullptr, DIM, DIM);
    ln_kernel<1><<<TOKENS, 256>>>(out, ln2_g, ln2_b, ah, al);
    gemm_tc<2,1><<<dim3(HIDDEN / 128, TOKENS / 128), 256, SMEM_SPLIT>>>(
        ah, al, w1h, w1l, b_fc1, nullptr, nullptr, f1h, f1l, nullptr, HIDDEN, DIM);
    gemm_tc<3,1><<<dim3(DIM / 128, TOKENS / 128), 256, SMEM_SPLIT>>>(
        f1h, f1l, w2h, w2l, b_fc2, out, out, nullptr, nullptr, nullptr, DIM, HIDDEN);
}

// round 16
// speedup vs baseline: 1.5824x; 1.0048x over previous
#include <cuda_runtime.h>
#include <cuda_fp16.h>
#include <math.h>
#include <stdint.h>

#define DIM 1024
#define HEADS 16
#define HEAD_DIM 64
#define HIDDEN 4096
#define BATCH 4
#define SEQ 2048
#define TOKENS (BATCH * SEQ)   // 8192
#define EPS 1e-5f

// ================= scratch (device globals) =================
__device__ __half g_a[TOKENS * DIM];          // LN1 out fp16 (single)
__device__ __half g_ah[TOKENS * DIM];         // LN2 out split hi
__device__ __half g_al[TOKENS * DIM];         // LN2 out split lo
__device__ __half g_q[TOKENS * DIM];          // [b*h][n][64], q pre-scaled 0.125*log2e
__device__ __half g_k[TOKENS * DIM];
__device__ __half g_v[TOKENS * DIM];
__device__ __half g_o[TOKENS * DIM];          // attn out [token][h*64+d]
__device__ __half g_f1h[TOKENS * HIDDEN];     // fc1+gelu out split
__device__ __half g_f1l[TOKENS * HIDDEN];
__device__ __half g_wqkvT[3 * DIM * DIM];     // [N,K] single
__device__ __half g_wprojT[DIM * DIM];        // single
__device__ __half g_wfc1T_h[HIDDEN * DIM];    // split
__device__ __half g_wfc1T_l[HIDDEN * DIM];
__device__ __half g_wfc2T_h[DIM * HIDDEN];
__device__ __half g_wfc2T_l[DIM * HIDDEN];

// ================= PTX helpers (plain sm_80+ PTX) =================
__device__ __forceinline__ uint32_t smem_u32(const void* p) {
    return (uint32_t)__cvta_generic_to_shared(p);
}
__device__ __forceinline__ void cp16(uint32_t dst, const void* src) {
    asm volatile("cp.async.cg.shared.global [%0], [%1], 16;" :: "r"(dst), "l"(src) : "memory");
}
__device__ __forceinline__ void cp_commit() {
    asm volatile("cp.async.commit_group;" ::: "memory");
}
__device__ __forceinline__ void cp_wait1() {
    asm volatile("cp.async.wait_group 1;" ::: "memory");
}
__device__ __forceinline__ void cp_wait0() {
    asm volatile("cp.async.wait_group 0;" ::: "memory");
}
__device__ __forceinline__ void ldm_x4(uint32_t* r, uint32_t addr) {
    asm volatile("ldmatrix.sync.aligned.m8n8.x4.shared.b16 {%0,%1,%2,%3}, [%4];"
                 : "=r"(r[0]), "=r"(r[1]), "=r"(r[2]), "=r"(r[3]) : "r"(addr));
}
__device__ __forceinline__ void ldm_x4t(uint32_t* r, uint32_t addr) {
    asm volatile("ldmatrix.sync.aligned.m8n8.x4.trans.shared.b16 {%0,%1,%2,%3}, [%4];"
                 : "=r"(r[0]), "=r"(r[1]), "=r"(r[2]), "=r"(r[3]) : "r"(addr));
}
__device__ __forceinline__ void mma_fp16(float* d, const uint32_t* a, const uint32_t* b) {
    asm volatile(
        "mma.sync.aligned.m16n8k16.row.col.f32.f16.f16.f32 "
        "{%0,%1,%2,%3}, {%4,%5,%6,%7}, {%8,%9}, {%0,%1,%2,%3};"
        : "+f"(d[0]), "+f"(d[1]), "+f"(d[2]), "+f"(d[3])
        : "r"(a[0]), "r"(a[1]), "r"(a[2]), "r"(a[3]), "r"(b[0]), "r"(b[1]));
}
__device__ __forceinline__ uint32_t pack_h2(float a, float b) {
    __half2 h = __floats2half2_rn(a, b);
    return *(uint32_t*)&h;
}
__device__ __forceinline__ void split16(float v, __half& h, __half& l) {
    h = __float2half_rn(v);
    l = __float2half_rn(v - __half2float(h));
}

// ================= LayerNorm =================
template<int SPLIT>
__global__ void ln_kernel(const float* __restrict__ x,
                          const float* __restrict__ g,
                          const float* __restrict__ b,
                          __half* __restrict__ o0, __half* __restrict__ o1)
{
    int row = blockIdx.x;
    const float4* xr = (const float4*)(x + (size_t)row * DIM);
    int tid = threadIdx.x;
    float4 v = xr[tid];
    float s  = v.x + v.y + v.z + v.w;
    float ss = v.x*v.x + v.y*v.y + v.z*v.z + v.w*v.w;
    for (int o = 16; o > 0; o >>= 1) {
        s  += __shfl_down_sync(0xFFFFFFFFu, s,  o);
        ss += __shfl_down_sync(0xFFFFFFFFu, ss, o);
    }
    __shared__ float red_s[8], red_ss[8];
    int wid = tid >> 5, lid = tid & 31;
    if (lid == 0) { red_s[wid] = s; red_ss[wid] = ss; }
    __syncthreads();
    __shared__ float sh_mu, sh_rstd;
    if (tid == 0) {
        float ts = 0.f, tss = 0.f;
        #pragma unroll
        for (int i = 0; i < 8; i++) { ts += red_s[i]; tss += red_ss[i]; }
        float mu  = ts * (1.0f / DIM);
        float var = tss * (1.0f / DIM) - mu * mu;
        sh_mu = mu; sh_rstd = rsqrtf(var + EPS);
    }
    __syncthreads();
    float mu = sh_mu, rstd = sh_rstd;

    int c = tid * 4;
    float4 gg = *(const float4*)(g + c);
    float4 bb = *(const float4*)(b + c);
    float y[4];
    y[0] = (v.x - mu) * rstd * gg.x + bb.x;
    y[1] = (v.y - mu) * rstd * gg.y + bb.y;
    y[2] = (v.z - mu) * rstd * gg.z + bb.z;
    y[3] = (v.w - mu) * rstd * gg.w + bb.w;
    size_t base = (size_t)row * DIM + c;
    #pragma unroll
    for (int i = 0; i < 4; i += 2) {
        if (SPLIT) {
            __half h0, l0, h1, l1;
            split16(y[i], h0, l0);
            split16(y[i+1], h1, l1);
            *(__half2*)(o0 + base + i) = __half2(h0, h1);
            *(__half2*)(o1 + base + i) = __half2(l0, l1);
        } else {
            *(__half2*)(o0 + base + i) = __floats2half2_rn(y[i], y[i+1]);
        }
    }
}

// ========== weight transpose: w[K,N] f32 -> [N,K] fp16 (single or split) ==========
template<int SPLIT>
__global__ void wT_kernel(const float* __restrict__ w,
                          __half* __restrict__ o0, __half* __restrict__ o1,
                          int K, int N)
{
    __shared__ float t[32][33];
    int n0 = blockIdx.x * 32, k0 = blockIdx.y * 32;
    int tx = threadIdx.x;   // 0..15
    int ty = threadIdx.y;   // 0..15
    #pragma unroll
    for (int r = 0; r < 2; r++) {
        int kk = ty + r * 16;
        float2 v = *(const float2*)(w + (size_t)(k0 + kk) * N + n0 + tx * 2);
        t[kk][tx * 2]     = v.x;
        t[kk][tx * 2 + 1] = v.y;
    }
    __syncthreads();
    #pragma unroll
    for (int r = 0; r < 2; r++) {
        int nn = ty + r * 16;
        float v0 = t[tx * 2][nn];
        float v1 = t[tx * 2 + 1][nn];
        size_t idx = (size_t)(n0 + nn) * K + k0 + tx * 2;
        if (SPLIT) {
            __half h0, l0, h1, l1;
            split16(v0, h0, l0);
            split16(v1, h1, l1);
            *(__half2*)(o0 + idx) = __half2(h0, h1);
            *(__half2*)(o1 + idx) = __half2(l0, l1);
        } else {
            *(__half2*)(o0 + idx) = __floats2half2_rn(v0, v1);
        }
    }
}

// ================= fp16 mma.sync GEMM (R15 + split holds bh/bl, reloads A) ========
// MODE 0: single, +bias, scatter QKV fp16 (q scaled 0.125*log2e)
// MODE 1: single, +bias+res -> f32
// MODE 2: split,  +bias, exact GELU -> split fp16 (O0=hi, O1=lo)
// MODE 3: split,  +bias+res -> f32
#define ROWB   80
#define TILE_B (128 * ROWB)            // 10240
#define BKK 32

template<int MODE, int SPLIT>
__global__ void __launch_bounds__(256, 2) gemm_tc(
    const __half* __restrict__ Ah, const __half* __restrict__ Al,
    const __half* __restrict__ Bh, const __half* __restrict__ Bl,
    const float* __restrict__ bias, const float* __restrict__ res,
    float* __restrict__ Cf, __half* __restrict__ O0,
    __half* __restrict__ O1, __half* __restrict__ O2,
    int Nt, int K)
{
    const int NTILES = SPLIT ? 4 : 2;
    const int STAGE_B = NTILES * TILE_B;
    const int NSTAGEL = SPLIT ? 2 : 3;     // split: 2 stages so 2 CTAs/SM fit
    extern __shared__ char smem[];
    uint32_t sb = smem_u32(smem);
    const int tid = threadIdx.x;
    const int w = tid >> 5;
    const int lane = tid & 31;
    const int m0 = blockIdx.y * 128;
    const int n0 = blockIdx.x * 128;
    const int warp_m = (w & 1) * 64;
    const int warp_n = (w >> 1) * 32;

    const __half* srcAh = Ah + (size_t)m0 * K;
    const __half* srcBh = Bh + (size_t)n0 * K;
    const __half* srcAl = SPLIT ? (Al + (size_t)m0 * K) : nullptr;
    const __half* srcBl = SPLIT ? (Bl + (size_t)n0 * K) : nullptr;

    auto load_stage = [&](int s, int k0) {
        uint32_t sdst = sb + s * STAGE_B;
        #pragma unroll
        for (int i = 0; i < 2; i++) {
            int idx = tid + i * 256;        // 0..511
            int row = idx >> 2, ch = idx & 3;
            uint32_t doff = row * ROWB + ch * 16;
            size_t soff = (size_t)row * K + k0 + ch * 8;
            cp16(sdst + doff, srcAh + soff);
            cp16(sdst + TILE_B + doff, srcBh + soff);
            if (SPLIT) {
                cp16(sdst + 2 * TILE_B + doff, srcAl + soff);
                cp16(sdst + 3 * TILE_B + doff, srcBl + soff);
            }
        }
    };

    float acc[4][4][4];
    #pragma unroll
    for (int i = 0; i < 4; i++)
        #pragma unroll
        for (int j = 0; j < 4; j++)
            #pragma unroll
            for (int d = 0; d < 4; d++) acc[i][j][d] = 0.f;

    const int NT = K / BKK;
    load_stage(0, 0);       cp_commit();
    load_stage(1, BKK);     cp_commit();

    const int lm  = lane & 15, kb4 = lane >> 4;
    // B-frag ldm_x4 lane map: matrix = lane>>3; one x4 loads bf[nf], bf[nf+1]
    const int brow4 = (lane >> 4) * 8 + (lane & 7);
    const int bchk4 = ((lane >> 3) & 1) * 8;

    for (int it = 0; it < NT; it++) {
        cp_wait1();
        __syncthreads();

        uint32_t stg = sb + (it % NSTAGEL) * STAGE_B;

        if (!SPLIT) {
            if (it + 2 < NT) { load_stage((it + 2) % NSTAGEL, (it + 2) * BKK); cp_commit(); }
        }

        #pragma unroll
        for (int ks = 0; ks < 2; ks++) {
            uint32_t aoff = (warp_m + lm) * ROWB + (ks * 16 + kb4 * 8) * 2;
            uint32_t boff4 = (warp_n + brow4) * ROWB + (ks * 16 + bchk4) * 2;

            if (SPLIT) {
                // hold bh + bl (one ldm_x4 each), reload only A: 12 LDSM/slice
                uint32_t af[4][4], bh_[4][2], bl_[4][2];
                #pragma unroll
                for (int mf = 0; mf < 4; mf++)
                    ldm_x4(af[mf], stg + aoff + mf * 16 * ROWB);                 // ah
                #pragma unroll
                for (int p = 0; p < 2; p++)
                    ldm_x4(&bh_[2*p][0], stg + TILE_B + boff4 + p * 16 * ROWB);  // bh
                #pragma unroll
                for (int p = 0; p < 2; p++)
                    ldm_x4(&bl_[2*p][0], stg + 3 * TILE_B + boff4 + p * 16 * ROWB); // bl

                #pragma unroll
                for (int mf = 0; mf < 4; mf++)
                    #pragma unroll
                    for (int nf = 0; nf < 4; nf++)
                        mma_fp16(acc[mf][nf], af[mf], bh_[nf]);                  // ah*bh
                #pragma unroll
                for (int mf = 0; mf < 4; mf++)
                    #pragma unroll
                    for (int nf = 0; nf < 4; nf++)
                        mma_fp16(acc[mf][nf], af[mf], bl_[nf]);                  // ah*bl

                #pragma unroll
                for (int mf = 0; mf < 4; mf++)
                    ldm_x4(af[mf], stg + 2 * TILE_B + aoff + mf * 16 * ROWB);    // al
                #pragma unroll
                for (int mf = 0; mf < 4; mf++)
                    #pragma unroll
                    for (int nf = 0; nf < 4; nf++)
                        mma_fp16(acc[mf][nf], af[mf], bh_[nf]);                  // al*bh
            } else {
                uint32_t af[4][4], bf[4][2];
                #pragma unroll
                for (int mf = 0; mf < 4; mf++)
                    ldm_x4(af[mf], stg + aoff + mf * 16 * ROWB);
                #pragma unroll
                for (int p = 0; p < 2; p++)
                    ldm_x4(&bf[2*p][0], stg + TILE_B + boff4 + p * 16 * ROWB);
                #pragma unroll
                for (int mf = 0; mf < 4; mf++)
                    #pragma unroll
                    for (int nf = 0; nf < 4; nf++)
                        mma_fp16(acc[mf][nf], af[mf], bf[nf]);
            }
        }
        if (SPLIT) {
            __syncthreads();
            if (it + 2 < NT) { load_stage((it + 2) % NSTAGEL, (it + 2) * BKK); cp_commit(); }
        }
    }

    // ---- epilogue ----
    const int r0 = lane >> 2, c0 = (lane & 3) * 2;
    #pragma unroll
    for (int mf = 0; mf < 4; mf++) {
        #pragma unroll
        for (int nf = 0; nf < 4; nf++) {
            int col = n0 + warp_n + nf * 8 + c0;
            float bv0 = bias[col], bv1 = bias[col + 1];
            #pragma unroll
            for (int h2 = 0; h2 < 2; h2++) {
                int row = m0 + warp_m + mf * 16 + r0 + h2 * 8;
                float v0 = acc[mf][nf][h2 * 2 + 0] + bv0;
                float v1 = acc[mf][nf][h2 * 2 + 1] + bv1;
                if (MODE == 0) {
                    int t = col >> 10, rem = col & 1023;
                    int hh = rem >> 6, d = rem & 63;
                    __half* dst = (t == 0) ? O0 : (t == 1) ? O1 : O2;
                    if (t == 0) {
                        v0 *= 0.18033688011112042f;  // 0.125 * log2(e)
                        v1 *= 0.18033688011112042f;
                    }
                    int b = row >> 11, n = row & 2047;
                    size_t idx = ((size_t)((b << 4) + hh) * SEQ + n) * HEAD_DIM + d;
                    *(__half2*)(dst + idx) = __floats2half2_rn(v0, v1);
                } else if (MODE == 2) {
                    v0 = 0.5f * v0 * (1.0f + erff(v0 * 0.70710678118654752f));
                    v1 = 0.5f * v1 * (1.0f + erff(v1 * 0.70710678118654752f));
                    __half h0, l0, h1, l1;
                    split16(v0, h0, l0);
                    split16(v1, h1, l1);
                    size_t idx = (size_t)row * Nt + col;
                    *(__half2*)(O0 + idx) = __half2(h0, h1);
                    *(__half2*)(O1 + idx) = __half2(l0, l1);
                } else {  // MODE 1 / 3
                    size_t idx = (size_t)row * Nt + col;
                    float2 rr = *(const float2*)(res + idx);
                    float2 o2; o2.x = v0 + rr.x; o2.y = v1 + rr.y;
                    *(float2*)(Cf + idx) = o2;
                }
            }
        }
    }
}

// ================= Flash attention (R15 config, unchanged) =================
#define AT_ROWB 144
#define AT_TILE (64 * AT_ROWB)            // 9216
#define ATTN_SMEM (AT_TILE * 5)           // Q + 2*(K,V) = 46080

__global__ void __launch_bounds__(128, 3) attn_kernel(
    const __half* __restrict__ qb, const __half* __restrict__ kb,
    const __half* __restrict__ vb, __half* __restrict__ ob)
{
    extern __shared__ char smc[];
    uint32_t sb = smem_u32(smc);
    const int tid = threadIdx.x;
    const int w = tid >> 5;
    const int lane = tid & 31;
    const int bh = blockIdx.y;
    const int n0 = blockIdx.x * 64;

    const __half* qg = qb + ((size_t)bh * SEQ + n0) * HEAD_DIM;

    #pragma unroll
    for (int i = 0; i < 4; i++) {
        int idx = tid + i * 128;
        int r = idx >> 3, ch = idx & 7;
        cp16(sb + r * AT_ROWB + ch * 16, qg + (size_t)r * HEAD_DIM + ch * 8);
    }
    cp_commit();

    auto loadKV = [&](int s, int t) {
        const __half* kg = kb + ((size_t)bh * SEQ + t * 64) * HEAD_DIM;
        const __half* vg = vb + ((size_t)bh * SEQ + t * 64) * HEAD_DIM;
        uint32_t ks = sb + AT_TILE + s * 2 * AT_TILE;
        uint32_t vs = ks + AT_TILE;
        #pragma unroll
        for (int i = 0; i < 4; i++) {
            int idx = tid + i * 128;
            int r = idx >> 3, ch = idx & 7;
            cp16(ks + r * AT_ROWB + ch * 16, kg + (size_t)r * HEAD_DIM + ch * 8);
            cp16(vs + r * AT_ROWB + ch * 16, vg + (size_t)r * HEAD_DIM + ch * 8);
        }
    };

    loadKV(0, 0); cp_commit();
    cp_wait1();
    __syncthreads();

    const int lm = lane & 15, kb4 = lane >> 4;
    uint32_t qf[4][4];
    #pragma unroll
    for (int kf = 0; kf < 4; kf++)
        ldm_x4(qf[kf], sb + (w * 16 + lm) * AT_ROWB + (kf * 16 + kb4 * 8) * 2);

    const int krow4 = lane & 7;
    const int kchk4 = (lane >> 3) * 16;

    float of[8][4];
    #pragma unroll
    for (int i = 0; i < 8; i++)
        #pragma unroll
        for (int j = 0; j < 4; j++) of[i][j] = 0.f;
    float m0 = -1e30f, m1 = -1e30f;
    float l0 = 0.f, l1 = 0.f;

    const int NTK = SEQ / 64;
    for (int t = 0; t < NTK; t++) {
        int s = t & 1;
        if (t + 1 < NTK) { loadKV(s ^ 1, t + 1); cp_commit(); }
        if (t + 1 < NTK) cp_wait1(); else cp_wait0();
        __syncthreads();

        uint32_t kbase = sb + AT_TILE + s * 2 * AT_TILE;
        uint32_t vbase = kbase + AT_TILE;

        float sc[8][4];
        #pragma unroll
        for (int i = 0; i < 8; i++)
            #pragma unroll
            for (int j = 0; j < 4; j++) sc[i][j] = 0.f;
        #pragma unroll
        for (int nf = 0; nf < 8; nf++) {
            uint32_t bf[4][2];
            uint32_t kat = kbase + (nf * 8 + krow4) * AT_ROWB + kchk4;
            #pragma unroll
            for (int p = 0; p < 2; p++)
                ldm_x4(&bf[2*p][0], kat + p * 64);
            #pragma unroll
            for (int kf = 0; kf < 4; kf++)
                mma_fp16(sc[nf], qf[kf], bf[kf]);
        }

        float mx0 = -1e30f, mx1 = -1e30f;
        #pragma unroll
        for (int nf = 0; nf < 8; nf++) {
            mx0 = fmaxf(mx0, fmaxf(sc[nf][0], sc[nf][1]));
            mx1 = fmaxf(mx1, fmaxf(sc[nf][2], sc[nf][3]));
        }
        mx0 = fmaxf(mx0, __shfl_xor_sync(0xFFFFFFFFu, mx0, 1));
        mx0 = fmaxf(mx0, __shfl_xor_sync(0xFFFFFFFFu, mx0, 2));
        mx1 = fmaxf(mx1, __shfl_xor_sync(0xFFFFFFFFu, mx1, 1));
        mx1 = fmaxf(mx1, __shfl_xor_sync(0xFFFFFFFFu, mx1, 2));
        float mn0 = fmaxf(m0, mx0), mn1 = fmaxf(m1, mx1);
        float fac0 = exp2f(m0 - mn0), fac1 = exp2f(m1 - mn1);
        m0 = mn0; m1 = mn1;
        float ls0 = 0.f, ls1 = 0.f;
        #pragma unroll
        for (int nf = 0; nf < 8; nf++) {
            sc[nf][0] = exp2f(sc[nf][0] - m0);
            sc[nf][1] = exp2f(sc[nf][1] - m0);
            sc[nf][2] = exp2f(sc[nf][2] - m1);
            sc[nf][3] = exp2f(sc[nf][3] - m1);
            ls0 += sc[nf][0] + sc[nf][1];
            ls1 += sc[nf][2] + sc[nf][3];
        }
        l0 = l0 * fac0 + ls0;
        l1 = l1 * fac1 + ls1;
        #pragma unroll
        for (int nf = 0; nf < 8; nf++) {
            of[nf][0] *= fac0; of[nf][1] *= fac0;
            of[nf][2] *= fac1; of[nf][3] *= fac1;
        }

        uint32_t pa[4][4];
        #pragma unroll
        for (int kf = 0; kf < 4; kf++) {
            pa[kf][0] = pack_h2(sc[2*kf][0],   sc[2*kf][1]);
            pa[kf][1] = pack_h2(sc[2*kf][2],   sc[2*kf][3]);
            pa[kf][2] = pack_h2(sc[2*kf+1][0], sc[2*kf+1][1]);
            pa[kf][3] = pack_h2(sc[2*kf+1][2], sc[2*kf+1][3]);
        }

        int tl = lane >> 3;
        #pragma unroll
        for (int kf = 0; kf < 4; kf++) {
            #pragma unroll
            for (int nb = 0; nb < 4; nb++) {
                uint32_t vf[4];
                int row = kf * 16 + (tl & 1) * 8 + (lane & 7);
                int col = nb * 16 + (tl >> 1) * 8;
                ldm_x4t(vf, vbase + row * AT_ROWB + col * 2);
                mma_fp16(of[2*nb],     pa[kf], vf);
                mma_fp16(of[2*nb + 1], pa[kf], vf + 2);
            }
        }
        __syncthreads();
    }

    l0 += __shfl_xor_sync(0xFFFFFFFFu, l0, 1);
    l0 += __shfl_xor_sync(0xFFFFFFFFu, l0, 2);
    l1 += __shfl_xor_sync(0xFFFFFFFFu, l1, 1);
    l1 += __shfl_xor_sync(0xFFFFFFFFu, l1, 2);

    float inv0 = 1.0f / l0, inv1 = 1.0f / l1;
    int b = bh >> 4, hh = bh & 15;
    int r0g = n0 + w * 16 + (lane >> 2);
    size_t tok0 = (size_t)(b * SEQ + r0g);
    size_t tok1 = tok0 + 8;
    int colb = hh * HEAD_DIM + 2 * (lane & 3);
    #pragma unroll
    for (int nf = 0; nf < 8; nf++) {
        int col = colb + nf * 8;
        *(__half2*)(ob + tok0 * DIM + col) = __floats2half2_rn(of[nf][0] * inv0, of[nf][1] * inv0);
        *(__half2*)(ob + tok1 * DIM + col) = __floats2half2_rn(of[nf][2] * inv1, of[nf][3] * inv1);
    }
}

// ================= launch =================
extern "C" void kernel_launch(void* const* d_in, const int* in_sizes, int n_in,
                              void* d_out, int out_size)
{
    (void)in_sizes; (void)n_in; (void)out_size;
    const float* x      = (const float*)d_in[0];
    const float* ln1_g  = (const float*)d_in[1];
    const float* ln1_b  = (const float*)d_in[2];
    const float* ln2_g  = (const float*)d_in[3];
    const float* ln2_b  = (const float*)d_in[4];
    const float* w_qkv  = (const float*)d_in[5];
    const float* b_qkv  = (const float*)d_in[6];
    const float* w_proj = (const float*)d_in[7];
    const float* b_proj = (const float*)d_in[8];
    const float* w_fc1  = (const float*)d_in[9];
    const float* b_fc1  = (const float*)d_in[10];
    const float* w_fc2  = (const float*)d_in[11];
    const float* b_fc2  = (const float*)d_in[12];
    float* out = (float*)d_out;

    __half *a, *ah, *al, *q, *k, *v, *o, *f1h, *f1l;
    __half *wq, *wp, *w1h, *w1l, *w2h, *w2l;
    cudaGetSymbolAddress((void**)&a,   g_a);
    cudaGetSymbolAddress((void**)&ah,  g_ah);
    cudaGetSymbolAddress((void**)&al,  g_al);
    cudaGetSymbolAddress((void**)&q,   g_q);
    cudaGetSymbolAddress((void**)&k,   g_k);
    cudaGetSymbolAddress((void**)&v,   g_v);
    cudaGetSymbolAddress((void**)&o,   g_o);
    cudaGetSymbolAddress((void**)&f1h, g_f1h);
    cudaGetSymbolAddress((void**)&f1l, g_f1l);
    cudaGetSymbolAddress((void**)&wq,  g_wqkvT);
    cudaGetSymbolAddress((void**)&wp,  g_wprojT);
    cudaGetSymbolAddress((void**)&w1h, g_wfc1T_h);
    cudaGetSymbolAddress((void**)&w1l, g_wfc1T_l);
    cudaGetSymbolAddress((void**)&w2h, g_wfc2T_h);
    cudaGetSymbolAddress((void**)&w2l, g_wfc2T_l);

    const int SMEM_SINGLE = 3 * 2 * TILE_B;   // 61440 (3 stages)
    const int SMEM_SPLIT  = 2 * 4 * TILE_B;   // 81920 (2 stages)
    cudaFuncSetAttribute(attn_kernel, cudaFuncAttributeMaxDynamicSharedMemorySize, ATTN_SMEM);
    cudaFuncSetAttribute((gemm_tc<0,0>), cudaFuncAttributeMaxDynamicSharedMemorySize, SMEM_SINGLE);
    cudaFuncSetAttribute((gemm_tc<1,0>), cudaFuncAttributeMaxDynamicSharedMemorySize, SMEM_SINGLE);
    cudaFuncSetAttribute((gemm_tc<2,1>), cudaFuncAttributeMaxDynamicSharedMemorySize, SMEM_SPLIT);
    cudaFuncSetAttribute((gemm_tc<3,1>), cudaFuncAttributeMaxDynamicSharedMemorySize, SMEM_SPLIT);

    // ---- side stream for all weight transposes (captured event fork-join) ----
    cudaStream_t s1;
    cudaStreamCreateWithFlags(&s1, cudaStreamNonBlocking);
    cudaEvent_t eFork, eQkvT, eJoin;
    cudaEventCreateWithFlags(&eFork, cudaEventDisableTiming);
    cudaEventCreateWithFlags(&eQkvT, cudaEventDisableTiming);
    cudaEventCreateWithFlags(&eJoin, cudaEventDisableTiming);

    dim3 tb(16, 16);
    cudaEventRecord(eFork, 0);
    cudaStreamWaitEvent(s1, eFork, 0);
    wT_kernel<0><<<dim3(3 * DIM / 32, DIM / 32), tb, 0, s1>>>(w_qkv, wq, nullptr, DIM, 3 * DIM);
    cudaEventRecord(eQkvT, s1);
    wT_kernel<0><<<dim3(DIM / 32, DIM / 32), tb, 0, s1>>>(w_proj, wp, nullptr, DIM, DIM);
    wT_kernel<1><<<dim3(HIDDEN / 32, DIM / 32), tb, 0, s1>>>(w_fc1, w1h, w1l, DIM, HIDDEN);
    wT_kernel<1><<<dim3(DIM / 32, HIDDEN / 32), tb, 0, s1>>>(w_fc2, w2h, w2l, HIDDEN, DIM);
    cudaEventRecord(eJoin, s1);

    // main stream
    ln_kernel<0><<<TOKENS, 256>>>(x, ln1_g, ln1_b, a, nullptr);
    cudaStreamWaitEvent(0, eQkvT, 0);
    gemm_tc<0,0><<<dim3(3 * DIM / 128, TOKENS / 128), 256, SMEM_SINGLE>>>(
        a, nullptr, wq, nullptr, b_qkv, nullptr, nullptr, q, k, v, 3 * DIM, DIM);
    attn_kernel<<<dim3(SEQ / 64, BATCH * HEADS), 128, ATTN_SMEM>>>(q, k, v, o);
    cudaStreamWaitEvent(0, eJoin, 0);
    gemm_tc<1,0><<<dim3(DIM / 128, TOKENS / 128), 256, SMEM_SINGLE>>>(
        o, nullptr, wp, nullptr, b_proj, x, out, nullptr, nullptr, nullptr, DIM, DIM);
    ln_kernel<1><<<TOKENS, 256>>>(out, ln2_g, ln2_b, ah, al);
    gemm_tc<2,1><<<dim3(HIDDEN / 128, TOKENS / 128), 256, SMEM_SPLIT>>>(
        ah, al, w1h, w1l, b_fc1, nullptr, nullptr, f1h, f1l, nullptr, HIDDEN, DIM);
    gemm_tc<3,1><<<dim3(DIM / 128, TOKENS / 128), 256, SMEM_SPLIT>>>(
        f1h, f1l, w2h, w2l, b_fc2, out, out, nullptr, nullptr, nullptr, DIM, HIDDEN);
}